// round 14
// baseline (speedup 1.0000x reference)
#include <cuda_runtime.h>
#include <cuda_bf16.h>
#include <math.h>

#define TT 4096
#define NB 2
#define NC 32

typedef __nv_bfloat16  bf;
typedef __nv_bfloat162 bf2;

// ----------------- static device scratch -----------------
__device__ __align__(16) float g_tokens[NB*TT*128];
__device__ __align__(16) float g_KV[NB*NC*128*128];
__device__ __align__(16) float g_Ksum[NB*NC*128];
__device__ __align__(16) float g_KsumX[NB*NC*128];
__device__ __align__(16) float g_rs[NB*TT*2];

__device__ __align__(16) bf g_x_h [NB*TT*128], g_x_l [NB*TT*128];
__device__ __align__(16) bf g_Qp_h[NB*TT*128], g_Qp_l[NB*TT*128];
__device__ __align__(16) bf g_Kp_h[NB*TT*128], g_Kp_l[NB*TT*128];
__device__ __align__(16) bf g_Vg_h[NB*TT*128], g_Vg_l[NB*TT*128];
__device__ __align__(16) bf g_As_h[NB*TT*128], g_As_l[NB*TT*128];
__device__ __align__(16) bf g_S_h [NB*NC*128*128], g_S_l [NB*NC*128*128];
__device__ __align__(16) bf g_at_h[NB*TT*128], g_at_l[NB*TT*128];
__device__ __align__(16) bf g_Wc_h[2*512*128],  g_Wc_l[2*512*128];
__device__ __align__(16) bf g_Wo_h[2*128*128],  g_Wo_l[2*128*128];

__device__ unsigned g_arrive;

// ----------------- helpers -----------------
__device__ __forceinline__ float phi_f(float x){ return x > 0.f ? x + 1.f : expf(x); }
__device__ __forceinline__ float sigm_f(float x){ return 1.f/(1.f+expf(-x)); }

__device__ __forceinline__ void split1(float v, bf* H, bf* L){
  bf h = __float2bfloat16(v);
  *H = h; *L = __float2bfloat16(v - __bfloat162float(h));
}
__device__ __forceinline__ bf2 split2(float v0, float v1, bf2* lo){
  bf h0=__float2bfloat16(v0), h1=__float2bfloat16(v1);
  *lo = __halves2bfloat162(__float2bfloat16(v0-__bfloat162float(h0)),
                           __float2bfloat16(v1-__bfloat162float(h1)));
  return __halves2bfloat162(h0,h1);
}
__device__ __forceinline__ unsigned bits2(bf2 v){ return *(unsigned*)&v; }

__device__ __forceinline__ unsigned sptr(const void* p){
  return (unsigned)__cvta_generic_to_shared(p);
}
__device__ __forceinline__ void ldsm4(unsigned addr, unsigned* r){
  asm volatile("ldmatrix.sync.aligned.m8n8.x4.shared.b16 {%0,%1,%2,%3}, [%4];"
    : "=r"(r[0]),"=r"(r[1]),"=r"(r[2]),"=r"(r[3]) : "r"(addr));
}
__device__ __forceinline__ void ldsm4t(unsigned addr, unsigned* r){
  asm volatile("ldmatrix.sync.aligned.m8n8.x4.trans.shared.b16 {%0,%1,%2,%3}, [%4];"
    : "=r"(r[0]),"=r"(r[1]),"=r"(r[2]),"=r"(r[3]) : "r"(addr));
}
__device__ __forceinline__ void mmab(float* c, const unsigned* a, unsigned b0, unsigned b1){
  asm volatile("mma.sync.aligned.m16n8k16.row.col.f32.bf16.bf16.f32 "
    "{%0,%1,%2,%3},{%4,%5,%6,%7},{%8,%9},{%0,%1,%2,%3};"
    : "+f"(c[0]),"+f"(c[1]),"+f"(c[2]),"+f"(c[3])
    : "r"(a[0]),"r"(a[1]),"r"(a[2]),"r"(a[3]),"r"(b0),"r"(b1));
}
__device__ __forceinline__ void cpa16(unsigned dst, const void* src){
  asm volatile("cp.async.cg.shared.global [%0], [%1], 16;" :: "r"(dst), "l"(src));
}
#define CPCOMMIT() asm volatile("cp.async.commit_group;")
#define CPWAIT(n)  asm volatile("cp.async.wait_group %0;" :: "n"(n))

__device__ __forceinline__ float warp_sum(float s){
#pragma unroll
  for(int o=16;o>0;o>>=1) s += __shfl_xor_sync(0xffffffffu, s, o);
  return s;
}

// ---------- device-wide barrier (all 256 blocks co-resident) ----------
__device__ __forceinline__ void gsync(unsigned bar){
  unsigned target = bar*256u;
  __syncthreads();
  if(threadIdx.x==0){
    __threadfence();
    atomicAdd(&g_arrive, 1u);
    while(*((volatile unsigned*)&g_arrive) < target) __nanosleep(64);
    __threadfence();
  }
  __syncthreads();
}

// ---------- cp.async tile loaders ----------
template<int ROWS>
__device__ __forceinline__ void cp_nat(const bf* __restrict__ Gh, const bf* __restrict__ Gl,
                                       size_t base, int ldg, int k0,
                                       bf* Sh, bf* Sl, int tid){
  if(2*ROWS>=256 || tid < 2*ROWS){
    int r = tid>>1, q = (tid&1)<<3;
    size_t off = base + (size_t)r*ldg + k0 + q;
    cpa16(sptr(Sh + r*24 + q), Gh + off);
    cpa16(sptr(Sl + r*24 + q), Gl + off);
  }
}
template<int COLS,int SSTR>
__device__ __forceinline__ void cp_trans(const bf* __restrict__ Gh, const bf* __restrict__ Gl,
                                         size_t base, int ldg, int k0, int n0,
                                         bf* Sh, bf* Sl, int tid){
  constexpr int CPT = COLS/8;
  if(16*CPT>=256 || tid < 16*CPT){
    int r = tid/CPT, c = (tid%CPT)<<3;
    size_t off = base + (size_t)(k0+r)*ldg + n0 + c;
    cpa16(sptr(Sh + r*SSTR + c), Gh + off);
    cpa16(sptr(Sl + r*SSTR + c), Gl + off);
  }
}

// ---------- one k16 bf16x3 mma stage ----------
template<int MT,int PN,bool AT,int ASTR,bool BT,int BSTR>
__device__ __forceinline__ void mma_stageP(const bf* AhS, const bf* AlS,
                                           const bf* BhS, const bf* BlS,
                                           float (*acc)[2*PN][4], int wm,int wn,int lane){
  unsigned ah[MT][4], al[MT][4];
#pragma unroll
  for(int mt=0;mt<MT;mt++){
    if(!AT){
      int r = wm*(MT*16)+mt*16 + (lane&15);
      int c = (lane&16)>>1;
      ldsm4 (sptr(AhS + r*ASTR + c), ah[mt]);
      ldsm4 (sptr(AlS + r*ASTR + c), al[mt]);
    }else{
      int r = (lane&7) + ((lane&16)>>1);
      int c = wm*(MT*16)+mt*16 + (lane&8);
      ldsm4t(sptr(AhS + r*ASTR + c), ah[mt]);
      ldsm4t(sptr(AlS + r*ASTR + c), al[mt]);
    }
  }
#pragma unroll
  for(int p=0;p<PN;p++){
    unsigned bh[4], bl[4];
    if(!BT){
      int r = wn*(PN*16)+p*16 + (lane&7) + ((lane>>1)&8);
      int c = lane&8;
      ldsm4 (sptr(BhS + r*BSTR + c), bh);
      ldsm4 (sptr(BlS + r*BSTR + c), bl);
    }else{
      int r = (lane&7) + (lane&8);
      int c = wn*(PN*16)+p*16 + ((lane&16)>>1);
      ldsm4t(sptr(BhS + r*BSTR + c), bh);
      ldsm4t(sptr(BlS + r*BSTR + c), bl);
    }
#pragma unroll
    for(int mt=0;mt<MT;mt++){
      mmab(acc[mt][2*p  ], ah[mt], bh[0],bh[1]);
      mmab(acc[mt][2*p  ], al[mt], bh[0],bh[1]);
      mmab(acc[mt][2*p  ], ah[mt], bl[0],bl[1]);
      mmab(acc[mt][2*p+1], ah[mt], bh[2],bh[3]);
      mmab(acc[mt][2*p+1], al[mt], bh[2],bh[3]);
      mmab(acc[mt][2*p+1], ah[mt], bl[2],bl[3]);
    }
  }
}

#define THREAD_IDS \
  int tid=threadIdx.x, lane=tid&31, wid=tid>>5, wm=wid>>1, wn=wid&1; \
  int gid=lane>>2, tig=lane&3; (void)gid; (void)tig;

// ----------------- build (separate first launch; resets barrier) -----------
__global__ void build_all(const float* __restrict__ xs, const float* __restrict__ ys,
                          const float* __restrict__ qx,
                          const float* __restrict__ Wq, const float* __restrict__ Wk,
                          const float* __restrict__ Wv, const float* __restrict__ Wg,
                          const float* __restrict__ Wo,
                          const float* __restrict__ l1w, const float* __restrict__ l1b){
  int bid = blockIdx.x;
  if(bid==0 && threadIdx.x==0) g_arrive = 0u;
  if(bid < 1024){
    int warp = threadIdx.x>>5, lane = threadIdx.x&31;
    int tok = bid*8 + warp;
    int b = tok>>12, t = tok&4095;
    float v[4];
#pragma unroll
    for(int j=0;j<4;j++){
      int d = lane*4 + j;
      if(t < 4095) v[j] = (d<127) ? xs[((size_t)b*4095+t)*127+d] : ys[(size_t)b*4095+t];
      else         v[j] = (d<127) ? qx[(size_t)b*127+d] : 0.f;
    }
    size_t idx = (size_t)tok*128 + lane*4;
    *(float4*)&g_tokens[idx] = make_float4(v[0],v[1],v[2],v[3]);
    float s = warp_sum(v[0]+v[1]+v[2]+v[3]);
    float q = warp_sum(v[0]*v[0]+v[1]*v[1]+v[2]*v[2]+v[3]*v[3]);
    float m = s*(1.f/128.f);
    float inv = rsqrtf(q*(1.f/128.f) - m*m + 1e-5f);
    float4 wv = *(const float4*)&l1w[lane*4];
    float4 bv = *(const float4*)&l1b[lane*4];
    float o0=(v[0]-m)*inv*wv.x+bv.x, o1=(v[1]-m)*inv*wv.y+bv.y;
    float o2=(v[2]-m)*inv*wv.z+bv.z, o3=(v[3]-m)*inv*wv.w+bv.w;
    bf2 l0,l1_; bf2 h0=split2(o0,o1,&l0), h1=split2(o2,o3,&l1_);
    *(uint2*)&g_x_h[idx] = make_uint2(bits2(h0), bits2(h1));
    *(uint2*)&g_x_l[idx] = make_uint2(bits2(l0), bits2(l1_));
  }else if(bid < 1536){
    int idx = (bid-1024)*256 + threadIdx.x;
    int l = idx >> 16;
    int r = idx & ((1<<16)-1);
    int n = r >> 7, k = r & 127;
    float v = 0.f;
    if(n < 127)        v = Wq[((size_t)l*127 + n)*128 + k];
    else if(n == 127)  v = 0.f;
    else if(n < 255)   v = Wk[((size_t)l*127 + (n-128))*128 + k];
    else if(n == 255)  v = 0.f;
    else if(n < 384)   v = Wv[((size_t)l*128 + (n-256))*128 + k];
    else               v = Wg[((size_t)l*128 + (n-384))*128 + k];
    split1(v, &g_Wc_h[idx], &g_Wc_l[idx]);
  }else{
    int idx = (bid-1536)*256 + threadIdx.x;
    split1(Wo[idx], &g_Wo_h[idx], &g_Wo_l[idx]);
  }
}

// ================= phase functions ==========================================
__device__ void proj_phase(int vb, char* SB, int l, const float* __restrict__ gb){
  THREAD_IDS;
  if(vb < 128){
    bf* Ahp=(bf*)SB; bf* Alp=(bf*)(SB+12288);
    bf* Bhp=(bf*)(SB+24576); bf* Blp=(bf*)(SB+36864);
    float acc[2][8][4];
#pragma unroll
    for(int i=0;i<2;i++)
#pragma unroll
      for(int j=0;j<8;j++)
#pragma unroll
        for(int k=0;k<4;k++) acc[i][j][k]=0.f;
    int y = vb>>6, xb = vb&63;
    size_t abase = (size_t)xb*128*128;
    size_t bbase = ((size_t)l*512 + y*128)*128;
    cp_nat<128>(g_x_h, g_x_l, abase, 128, 0, Ahp, Alp, tid);
    cp_nat<128>(g_Wc_h,g_Wc_l,bbase, 128, 0, Bhp, Blp, tid);
    CPCOMMIT();
    for(int s=0;s<8;s++){
      CPWAIT(0);
      __syncthreads();
      if(s<7){
        int nb=(s+1)&1;
        cp_nat<128>(g_x_h, g_x_l, abase, 128, (s+1)*16, Ahp+nb*3072, Alp+nb*3072, tid);
        cp_nat<128>(g_Wc_h,g_Wc_l,bbase, 128, (s+1)*16, Bhp+nb*3072, Blp+nb*3072, tid);
        CPCOMMIT();
      }
      int cb=s&1;
      mma_stageP<2,4,false,24,false,24>(Ahp+cb*3072,Alp+cb*3072,Bhp+cb*3072,Blp+cb*3072,acc,wm,wn,lane);
    }
    bf* Dh = y ? g_Kp_h : g_Qp_h;
    bf* Dl = y ? g_Kp_l : g_Qp_l;
    float sc[16];
#pragma unroll
    for(int j=0;j<16;j++) sc[j]=0.f;
#pragma unroll
    for(int mt=0;mt<2;mt++){
      int r0 = wm*32+mt*16+gid;
#pragma unroll
      for(int nt=0;nt<8;nt++){
        int col = wn*64+nt*8+tig*2;
        float* a = acc[mt][nt];
        float v0 = (col  <127)? phi_f(a[0]) : 0.f;
        float v1 = (col+1<127)? phi_f(a[1]) : 0.f;
        float v2 = (col  <127)? phi_f(a[2]) : 0.f;
        float v3 = (col+1<127)? phi_f(a[3]) : 0.f;
        sc[2*nt] += v0+v2; sc[2*nt+1] += v1+v3;
        bf2 lo;
        bf2 hi = split2(v0,v1,&lo);
        *(bf2*)&Dh[abase + (size_t)r0*128+col] = hi;
        *(bf2*)&Dl[abase + (size_t)r0*128+col] = lo;
        hi = split2(v2,v3,&lo);
        *(bf2*)&Dh[abase + (size_t)(r0+8)*128+col] = hi;
        *(bf2*)&Dl[abase + (size_t)(r0+8)*128+col] = lo;
      }
    }
    if(y==1){
#pragma unroll
      for(int j=0;j<16;j++){
        sc[j] += __shfl_xor_sync(0xffffffffu, sc[j], 4);
        sc[j] += __shfl_xor_sync(0xffffffffu, sc[j], 8);
        sc[j] += __shfl_xor_sync(0xffffffffu, sc[j], 16);
      }
      __syncthreads();
      float (*KsP)[128] = (float(*)[128])SB;
      if(lane<4){
#pragma unroll
        for(int j=0;j<16;j++){
          int col = wn*64 + (j>>1)*8 + lane*2 + (j&1);
          KsP[wm][col] = sc[j];
        }
      }
      __syncthreads();
      if(tid<128)
        g_Ksum[(size_t)xb*128 + tid] = KsP[0][tid]+KsP[1][tid]+KsP[2][tid]+KsP[3][tid];
    }
  }else{
    bf* Ahp=(bf*)SB; bf* Alp=(bf*)(SB+6144);
    bf* Bhp=(bf*)(SB+12288); bf* Blp=(bf*)(SB+24576);
    float accV[1][8][4], accG[1][8][4];
#pragma unroll
    for(int j=0;j<8;j++)
#pragma unroll
      for(int k=0;k<4;k++){ accV[0][j][k]=0.f; accG[0][j][k]=0.f; }
    int xb = vb - 128;
    size_t abase  = (size_t)xb*64*128;
    size_t bbaseV = ((size_t)l*512 + 256)*128;
    size_t bbaseG = ((size_t)l*512 + 384)*128;
    cp_nat<64> (g_x_h, g_x_l, abase,  128, 0, Ahp, Alp, tid);
    cp_nat<128>(g_Wc_h,g_Wc_l,bbaseV, 128, 0, Bhp, Blp, tid);
    CPCOMMIT();
    for(int s=0;s<16;s++){
      CPWAIT(0);
      __syncthreads();
      if(s<15){
        int s1=s+1, nb=s1&1;
        size_t bb = (s1<8)? bbaseV : bbaseG;
        cp_nat<64> (g_x_h, g_x_l, abase, 128, (s1&7)*16, Ahp+nb*1536, Alp+nb*1536, tid);
        cp_nat<128>(g_Wc_h,g_Wc_l,bb,    128, (s1&7)*16, Bhp+nb*3072, Blp+nb*3072, tid);
        CPCOMMIT();
      }
      int cb=s&1;
      float (*ac)[8][4] = (s<8)? accV : accG;
      mma_stageP<1,4,false,24,false,24>(Ahp+cb*1536,Alp+cb*1536,Bhp+cb*3072,Blp+cb*3072,ac,wm,wn,lane);
    }
    int r0 = wm*16+gid;
#pragma unroll
    for(int nt=0;nt<8;nt++){
      int col = wn*64+nt*8+tig*2;
      float* v = accV[0][nt];
      float* g = accG[0][nt];
      float gb0 = gb[col], gb1 = gb[col+1];
      float o0 = v[0]*sigm_f(g[0]+gb0), o1 = v[1]*sigm_f(g[1]+gb1);
      float o2 = v[2]*sigm_f(g[2]+gb0), o3 = v[3]*sigm_f(g[3]+gb1);
      bf2 lo;
      bf2 hi = split2(o0,o1,&lo);
      *(bf2*)&g_Vg_h[abase + (size_t)r0*128+col] = hi;
      *(bf2*)&g_Vg_l[abase + (size_t)r0*128+col] = lo;
      hi = split2(o2,o3,&lo);
      *(bf2*)&g_Vg_h[abase + (size_t)(r0+8)*128+col] = hi;
      *(bf2*)&g_Vg_l[abase + (size_t)(r0+8)*128+col] = lo;
    }
  }
}

// chunk1: vb<128 -> KV 64-col slices (triple-buffered); vb>=128 -> score 64-col halves (double-buffered, R8 shape)
__device__ void chunk1_phase(int vb, char* SB){
  THREAD_IDS;
  if(vb < 128){
    int c = vb & 31, b = (vb>>5)&1, z = vb>>6;
    size_t base = ((size_t)b*TT + c*128)*128;
    bf* Ah=(bf*)SB;            bf* Al=(bf*)(SB+13056);
    bf* Bh=(bf*)(SB+26112);    bf* Bl=(bf*)(SB+33024);
    float acc[2][4][4];
#pragma unroll
    for(int i=0;i<2;i++)
#pragma unroll
      for(int j=0;j<4;j++)
#pragma unroll
        for(int k=0;k<4;k++) acc[i][j][k]=0.f;
    int n0 = z*64;
#define KV_ISSUE(s) { \
      cp_trans<128,136>(g_Kp_h,g_Kp_l, base,128,(s)*16, 0,  Ah+((s)%3)*2176, Al+((s)%3)*2176, tid); \
      cp_trans<64, 72>(g_Vg_h,g_Vg_l, base,128,(s)*16, n0, Bh+((s)%3)*1152, Bl+((s)%3)*1152, tid); \
      CPCOMMIT(); }
    KV_ISSUE(0); KV_ISSUE(1);
    for(int s=0;s<8;s++){
      if(s<7) CPWAIT(1); else CPWAIT(0);
      __syncthreads();
      if(s+2<8) KV_ISSUE(s+2);
      int cb=s%3;
      mma_stageP<2,2,true,136,true,72>(Ah+cb*2176,Al+cb*2176,Bh+cb*1152,Bl+cb*1152,acc,wm,wn,lane);
    }
#undef KV_ISSUE
    float* C = g_KV + (size_t)(b*NC + c)*16384 + n0;
#pragma unroll
    for(int mt=0;mt<2;mt++){
      int r0 = wm*32+mt*16+gid;
#pragma unroll
      for(int nt=0;nt<4;nt++){
        int col = wn*32+nt*8+tig*2;
        float* a = acc[mt][nt];
        *(float2*)&C[(size_t)r0*128+col]     = make_float2(a[0],a[1]);
        *(float2*)&C[(size_t)(r0+8)*128+col] = make_float2(a[2],a[3]);
      }
    }
  }else{
    int r = vb - 128;
    int c = r & 31, b = (r>>5)&1, zz = r>>6;
    size_t base = ((size_t)b*TT + c*128)*128;
    bf* Ahp=(bf*)SB;            bf* Alp=(bf*)(SB+12288);
    bf* Bhp=(bf*)(SB+24576);    bf* Blp=(bf*)(SB+30720);
    float (*rs2s)[2] = (float(*)[2])(SB+36864);
    float acc[2][4][4];
#pragma unroll
    for(int i=0;i<2;i++)
#pragma unroll
      for(int j=0;j<4;j++)
#pragma unroll
        for(int k=0;k<4;k++) acc[i][j][k]=0.f;
    size_t bbase = base + (size_t)(zz*64)*128;
    cp_nat<128>(g_Qp_h,g_Qp_l, base, 128, 0, Ahp, Alp, tid);
    cp_nat<64> (g_Kp_h,g_Kp_l, bbase,128, 0, Bhp, Blp, tid);
    CPCOMMIT();
    for(int s=0;s<8;s++){
      CPWAIT(0);
      __syncthreads();
      if(s<7){
        int nb=(s+1)&1;
        cp_nat<128>(g_Qp_h,g_Qp_l, base, 128,(s+1)*16, Ahp+nb*3072, Alp+nb*3072, tid);
        cp_nat<64> (g_Kp_h,g_Kp_l, bbase,128,(s+1)*16, Bhp+nb*1536, Blp+nb*1536, tid);
        CPCOMMIT();
      }
      int cb=s&1;
      mma_stageP<2,2,false,24,false,24>(Ahp+cb*3072,Alp+cb*3072,Bhp+cb*1536,Blp+cb*1536,acc,wm,wn,lane);
    }
#pragma unroll
    for(int mt=0;mt<2;mt++){
      int r0 = wm*32+mt*16+gid;
      float s0=0.f, s1=0.f;
#pragma unroll
      for(int nt=0;nt<4;nt++){
        int col = zz*64 + wn*32 + nt*8 + tig*2;
        float* a = acc[mt][nt];
        float v0 = (col   <= r0  )? a[0] : 0.f;
        float v1 = (col+1 <= r0  )? a[1] : 0.f;
        float v2 = (col   <= r0+8)? a[2] : 0.f;
        float v3 = (col+1 <= r0+8)? a[3] : 0.f;
        s0 += v0+v1; s1 += v2+v3;
        bf2 lo;
        bf2 hi = split2(v0,v1,&lo);
        *(bf2*)&g_As_h[base + (size_t)r0*128+col] = hi;
        *(bf2*)&g_As_l[base + (size_t)r0*128+col] = lo;
        hi = split2(v2,v3,&lo);
        *(bf2*)&g_As_h[base + (size_t)(r0+8)*128+col] = hi;
        *(bf2*)&g_As_l[base + (size_t)(r0+8)*128+col] = lo;
      }
      s0 += __shfl_xor_sync(0xffffffffu, s0, 1); s0 += __shfl_xor_sync(0xffffffffu, s0, 2);
      s1 += __shfl_xor_sync(0xffffffffu, s1, 1); s1 += __shfl_xor_sync(0xffffffffu, s1, 2);
      if(tig==0){ rs2s[r0][wn]=s0; rs2s[r0+8][wn]=s1; }
    }
    __syncthreads();
    if(tid<128)
      g_rs[((size_t)b*TT + c*128 + tid)*2 + zz] = rs2s[tid][0] + rs2s[tid][1];
  }
}

__device__ void scan_phase(int vb, char* SB){
  float4 (*gt)[32] = (float4(*)[32])SB;
  int h = vb & 127, b = vb >> 7;
  int q = threadIdx.x & 31, g = threadIdx.x >> 5;
  size_t rowbase = (((size_t)b*NC)*128 + h)*128 + q*4;
  float4 v[4], pre[4];
#pragma unroll
  for(int j=0;j<4;j++) v[j] = *(const float4*)&g_KV[rowbase + (size_t)(g*4+j)*16384];
  float4 loc = make_float4(0.f,0.f,0.f,0.f);
#pragma unroll
  for(int j=0;j<4;j++){
    pre[j] = loc;
    loc.x += v[j].x; loc.y += v[j].y; loc.z += v[j].z; loc.w += v[j].w;
  }
  gt[g][q] = loc;
  __syncthreads();
  float4 off = make_float4(0.f,0.f,0.f,0.f);
#pragma unroll
  for(int gg=0;gg<7;gg++) if(gg < g){
    float4 t = gt[gg][q];
    off.x += t.x; off.y += t.y; off.z += t.z; off.w += t.w;
  }
#pragma unroll
  for(int j=0;j<4;j++){
    size_t i = rowbase + (size_t)(g*4+j)*16384;
    float a0 = off.x + pre[j].x, a1 = off.y + pre[j].y;
    float a2 = off.z + pre[j].z, a3 = off.w + pre[j].w;
    bf2 lo0, lo1;
    bf2 hi0 = split2(a0, a1, &lo0);
    bf2 hi1 = split2(a2, a3, &lo1);
    *(uint2*)&g_S_h[i] = make_uint2(bits2(hi0), bits2(hi1));
    *(uint2*)&g_S_l[i] = make_uint2(bits2(lo0), bits2(lo1));
  }
  if(threadIdx.x < NC){
    int mm = threadIdx.x;
    float ks = g_Ksum[(size_t)(b*NC + mm)*128 + h];
    float x = ks;
#pragma unroll
    for(int o=1;o<NC;o<<=1){
      float y = __shfl_up_sync(0xffffffffu, x, o);
      if(mm>=o) x += y;
    }
    g_KsumX[(size_t)(b*NC + mm)*128 + h] = x - ks;
  }
}

__device__ void num_phase(int vb, char* SB){
  bf* Ah=(bf*)SB;          bf* Al=(bf*)(SB+18432);
  bf* Bh=(bf*)(SB+36864);  bf* Bl=(bf*)(SB+40704);
  float* kx  = (float*)(SB+44544);
  float* dsm = (float*)(SB+45056);
  THREAD_IDS;
  int c = vb & 31, b = (vb>>5)&1, z = vb>>6;
  int n0 = z*32;
  size_t base  = ((size_t)b*TT + c*128)*128;
  size_t sbase = (size_t)(b*NC + c)*16384;
  float acc[2][2][4];
#pragma unroll
  for(int i=0;i<2;i++)
#pragma unroll
    for(int j=0;j<2;j++)
#pragma unroll
      for(int k=0;k<4;k++) acc[i][j][k]=0.f;
  if(tid<128) kx[tid] = g_KsumX[(size_t)(b*NC + c)*128 + tid];
  float dd = 0.f;
#define NUM_ISSUE(s) { \
    if((s)<8){ \
      cp_nat<128>   (g_As_h,g_As_l, base,128,(s)*16,     Ah+((s)%3)*3072, Al+((s)%3)*3072, tid); \
      cp_trans<32,40>(g_Vg_h,g_Vg_l, base,128,(s)*16, n0, Bh+((s)%3)*640,  Bl+((s)%3)*640,  tid); \
    }else{ \
      cp_nat<128>   (g_Qp_h,g_Qp_l, base, 128,((s)-8)*16,     Ah+((s)%3)*3072, Al+((s)%3)*3072, tid); \
      cp_trans<32,40>(g_S_h, g_S_l, sbase,128,((s)-8)*16, n0, Bh+((s)%3)*640,  Bl+((s)%3)*640,  tid); \
    } \
    CPCOMMIT(); }
  NUM_ISSUE(0); NUM_ISSUE(1);
  for(int s=0;s<16;s++){
    if(s<15) CPWAIT(1); else CPWAIT(0);
    __syncthreads();
    if(s+2<16) NUM_ISSUE(s+2);
    int cb=s%3;
    mma_stageP<2,1,false,24,true,40>(Ah+cb*3072,Al+cb*3072,Bh+cb*640,Bl+cb*640,acc,wm,wn,lane);
    if(s>=8 && tid<128){
      const bf* ac  = Ah + cb*3072 + tid*24;
      const bf* alc = Al + cb*3072 + tid*24;
      int kb = (s-8)*16;
#pragma unroll
      for(int k=0;k<16;k++)
        dd += (__bfloat162float(ac[k])+__bfloat162float(alc[k])) * kx[kb+k];
    }
  }
#undef NUM_ISSUE
  if(tid<128){
    size_t bt2 = ((size_t)b*TT + c*128 + tid)*2;
    dsm[tid] = fmaxf(g_rs[bt2] + g_rs[bt2+1] + dd, 1e-6f);
  }
  __syncthreads();
#pragma unroll
  for(int mt=0;mt<2;mt++){
    int r0 = wm*32+mt*16+gid;
    float inv0 = 1.f/dsm[r0], inv1 = 1.f/dsm[r0+8];
#pragma unroll
    for(int nt=0;nt<2;nt++){
      int col = n0 + wn*16 + nt*8 + tig*2;
      float* a = acc[mt][nt];
      bf2 lo;
      bf2 hi = split2(a[0]*inv0, a[1]*inv0, &lo);
      *(bf2*)&g_at_h[base + (size_t)r0*128+col] = hi;
      *(bf2*)&g_at_l[base + (size_t)r0*128+col] = lo;
      hi = split2(a[2]*inv1, a[3]*inv1, &lo);
      *(bf2*)&g_at_h[base + (size_t)(r0+8)*128+col] = hi;
      *(bf2*)&g_at_l[base + (size_t)(r0+8)*128+col] = lo;
    }
  }
}

// wo: 256 blocks of 32 rows (2x4 warp grid). Last layer: (vb&127)==127 -> pred.
__device__ void wo_phase(int vb, char* SB, int l,
                         const float* __restrict__ w2, const float* __restrict__ b2,
                         const float* __restrict__ w1, const float* __restrict__ b1,
                         int do_ln1, const float* __restrict__ pw, float* __restrict__ out){
  bf* Ahp=(bf*)SB;          bf* Alp=(bf*)(SB+3072);
  bf* Bhp=(bf*)(SB+6144);   bf* Blp=(bf*)(SB+18432);
  float (*Ps)[16] = (float(*)[16])(SB+30720);
  float (*Qs)[16] = (float(*)[16])(SB+32768);
  float* Mu  = (float*)(SB+34816);
  float* Rv  = (float*)(SB+34944);
  float* rr2 = (float*)(SB+35072);
  int tid=threadIdx.x, lane=tid&31, wid=tid>>5;
  int wm=wid>>2, wn=wid&3;
  int gid=lane>>2, tig=lane&3;
  float acc[1][4][4];
#pragma unroll
  for(int j=0;j<4;j++)
#pragma unroll
    for(int k=0;k<4;k++) acc[0][j][k]=0.f;
  size_t abase = (size_t)vb*32*128;
  size_t bbase = (size_t)l*16384;
  cp_nat<32> (g_at_h,g_at_l, abase,128, 0, Ahp, Alp, tid);
  cp_nat<128>(g_Wo_h,g_Wo_l, bbase,128, 0, Bhp, Blp, tid);
  CPCOMMIT();
  for(int s=0;s<8;s++){
    CPWAIT(0);
    __syncthreads();
    if(s<7){
      int nb=(s+1)&1;
      cp_nat<32> (g_at_h,g_at_l, abase,128,(s+1)*16, Ahp+nb*768,  Alp+nb*768,  tid);
      cp_nat<128>(g_Wo_h,g_Wo_l, bbase,128,(s+1)*16, Bhp+nb*3072, Blp+nb*3072, tid);
      CPCOMMIT();
    }
    int cb=s&1;
    mma_stageP<1,2,false,24,false,24>(Ahp+cb*768,Alp+cb*768,Bhp+cb*3072,Blp+cb*3072,acc,wm,wn,lane);
  }
  int slot = wn*4 + tig;
  size_t row0 = (size_t)vb*32;
  int rl0 = wm*16+gid;
  {
    float s0=0.f,q0=0.f,s1=0.f,q1=0.f;
#pragma unroll
    for(int nt=0;nt<4;nt++){
      int col = wn*32+nt*8+tig*2;
      float* a = acc[0][nt];
      float x0 = g_tokens[(row0+rl0)*128+col  ] + 0.1f*a[0];
      float x1 = g_tokens[(row0+rl0)*128+col+1] + 0.1f*a[1];
      float x2 = g_tokens[(row0+rl0+8)*128+col  ] + 0.1f*a[2];
      float x3 = g_tokens[(row0+rl0+8)*128+col+1] + 0.1f*a[3];
      a[0]=x0; a[1]=x1; a[2]=x2; a[3]=x3;
      s0 += x0+x1; q0 += x0*x0+x1*x1;
      s1 += x2+x3; q1 += x2*x2+x3*x3;
    }
    Ps[rl0][slot]=s0; Qs[rl0][slot]=q0;
    Ps[rl0+8][slot]=s1; Qs[rl0+8][slot]=q1;
  }
  __syncthreads();
  if(tid < 32){
    float s=0.f,q=0.f;
#pragma unroll
    for(int j=0;j<16;j++){ s+=Ps[tid][j]; q+=Qs[tid][j]; }
    float m = s*(1.f/128.f);
    float v = q*(1.f/128.f) - m*m;
    Mu[tid]=m; Rv[tid]=rsqrtf(v + 1e-5f);
  }
  __syncthreads();
  {
    float m0=Mu[rl0], i0=Rv[rl0], m1=Mu[rl0+8], i1=Rv[rl0+8];
    float s0=0.f,q0=0.f,s1=0.f,q1=0.f;
#pragma unroll
    for(int nt=0;nt<4;nt++){
      int col = wn*32+nt*8+tig*2;
      float* a = acc[0][nt];
      float w0=w2[col], w1_=w2[col+1], bb0=b2[col], bb1=b2[col+1];
      float y0=(a[0]-m0)*i0*w0+bb0, y1=(a[1]-m0)*i0*w1_+bb1;
      float y2=(a[2]-m1)*i1*w0+bb0, y3=(a[3]-m1)*i1*w1_+bb1;
      *(float2*)&g_tokens[(row0+rl0)*128+col]   = make_float2(y0,y1);
      *(float2*)&g_tokens[(row0+rl0+8)*128+col] = make_float2(y2,y3);
      a[0]=y0; a[1]=y1; a[2]=y2; a[3]=y3;
      s0 += y0+y1; q0 += y0*y0+y1*y1;
      s1 += y2+y3; q1 += y2*y2+y3*y3;
    }
    if(do_ln1){ Ps[rl0][slot]=s0; Qs[rl0][slot]=q0; Ps[rl0+8][slot]=s1; Qs[rl0+8][slot]=q1; }
  }
  if(!do_ln1){
    if((vb & 127) == 127){
      __syncthreads();
      int bb = vb >> 7;
      float v = 0.f;
      if(tid < 128) v = g_tokens[((size_t)bb*TT + (TT-1))*128 + tid] * pw[tid];
#pragma unroll
      for(int o=16;o>0;o>>=1) v += __shfl_down_sync(0xffffffffu, v, o);
      if(lane==0) rr2[wid]=v;
      __syncthreads();
      if(tid==0){
        float s=0.f;
#pragma unroll
        for(int j=0;j<8;j++) s+=rr2[j];
        out[bb] = s;
      }
    }
    return;
  }
  __syncthreads();
  if(tid < 32){
    float s=0.f,q=0.f;
#pragma unroll
    for(int j=0;j<16;j++){ s+=Ps[tid][j]; q+=Qs[tid][j]; }
    float m = s*(1.f/128.f);
    float v = q*(1.f/128.f) - m*m;
    Mu[tid]=m; Rv[tid]=rsqrtf(v + 1e-5f);
  }
  __syncthreads();
  {
    float m0=Mu[rl0], i0=Rv[rl0], m1=Mu[rl0+8], i1=Rv[rl0+8];
#pragma unroll
    for(int nt=0;nt<4;nt++){
      int col = wn*32+nt*8+tig*2;
      float* a = acc[0][nt];
      float w0=w1[col], w1_=w1[col+1], bb0=b1[col], bb1=b1[col+1];
      float y0=(a[0]-m0)*i0*w0+bb0, y1=(a[1]-m0)*i0*w1_+bb1;
      float y2=(a[2]-m1)*i1*w0+bb0, y3=(a[3]-m1)*i1*w1_+bb1;
      bf2 lo;
      bf2 hi = split2(y0,y1,&lo);
      *(bf2*)&g_x_h[(row0+rl0)*128+col] = hi;
      *(bf2*)&g_x_l[(row0+rl0)*128+col] = lo;
      hi = split2(y2,y3,&lo);
      *(bf2*)&g_x_h[(row0+rl0+8)*128+col] = hi;
      *(bf2*)&g_x_l[(row0+rl0+8)*128+col] = lo;
    }
  }
}

// ================= mega kernel: both layers, device barriers ================
__global__ void __launch_bounds__(256,2)
mega_kernel(const float* __restrict__ Wgb,
            const float* __restrict__ ln1w, const float* __restrict__ ln1b,
            const float* __restrict__ ln2w, const float* __restrict__ ln2b,
            const float* __restrict__ pw, float* __restrict__ out){
  extern __shared__ char SB[];
  int vb = blockIdx.x;
  unsigned bar = 0;
  for(int l=0;l<2;l++){
    proj_phase(vb, SB, l, Wgb + l*128);
    gsync(++bar);
    chunk1_phase(vb, SB);
    gsync(++bar);
    scan_phase(vb, SB);
    gsync(++bar);
    num_phase(vb, SB);
    gsync(++bar);
    wo_phase(vb, SB, l, ln2w + l*128, ln2b + l*128,
             ln1w + (l+1<2?(l+1):l)*128, ln1b + (l+1<2?(l+1):l)*128,
             l+1 < 2, pw, out);
    if(l==0) gsync(++bar);
  }
}

// ----------------- launch -----------------
extern "C" void kernel_launch(void* const* d_in, const int* in_sizes, int n_in,
                              void* d_out, int out_size){
  const float* xs   = (const float*)d_in[0];
  const float* ys   = (const float*)d_in[1];
  const float* qx   = (const float*)d_in[2];
  const float* Wq   = (const float*)d_in[3];
  const float* Wk   = (const float*)d_in[4];
  const float* Wv   = (const float*)d_in[5];
  const float* Wgw  = (const float*)d_in[6];
  const float* Wgb  = (const float*)d_in[7];
  const float* Wo   = (const float*)d_in[8];
  const float* ln1w = (const float*)d_in[9];
  const float* ln1b = (const float*)d_in[10];
  const float* ln2w = (const float*)d_in[11];
  const float* ln2b = (const float*)d_in[12];
  const float* pw   = (const float*)d_in[13];
  float* out = (float*)d_out;

  build_all<<<1664, 256>>>(xs, ys, qx, Wq, Wk, Wv, Wgw, Wo, ln1w, ln1b);
  mega_kernel<<<256, 256, 49152>>>(Wgb, ln1w, ln1b, ln2w, ln2b, pw, out);
}

// round 15
// speedup vs baseline: 1.0689x; 1.0689x over previous
#include <cuda_runtime.h>
#include <cuda_bf16.h>
#include <math.h>

#define TT 4096
#define NB 2
#define NC 32

typedef __nv_bfloat16  bf;
typedef __nv_bfloat162 bf2;

// ----------------- static device scratch -----------------
__device__ __align__(16) float g_tokens[NB*TT*128];
__device__ __align__(16) float g_KV[NB*NC*128*128];
__device__ __align__(16) float g_Ksum[NB*NC*128];
__device__ __align__(16) float g_KsumX[NB*NC*128];
__device__ __align__(16) float g_rs[NB*TT*2];

__device__ __align__(16) bf g_x_h [NB*TT*128], g_x_l [NB*TT*128];
__device__ __align__(16) bf g_Qp_h[NB*TT*128], g_Qp_l[NB*TT*128];
__device__ __align__(16) bf g_Kp_h[NB*TT*128], g_Kp_l[NB*TT*128];
__device__ __align__(16) bf g_Vg_h[NB*TT*128], g_Vg_l[NB*TT*128];
__device__ __align__(16) bf g_As_h[NB*TT*128], g_As_l[NB*TT*128];
__device__ __align__(16) bf g_S_h [NB*NC*128*128], g_S_l [NB*NC*128*128];
__device__ __align__(16) bf g_at_h[NB*TT*128], g_at_l[NB*TT*128];
__device__ __align__(16) bf g_Wc_h[2*512*128],  g_Wc_l[2*512*128];
__device__ __align__(16) bf g_Wo_h[2*128*128],  g_Wo_l[2*128*128];

__device__ unsigned g_arrive;

// ----------------- helpers -----------------
__device__ __forceinline__ float phi_f(float x){ return x > 0.f ? x + 1.f : expf(x); }
__device__ __forceinline__ float sigm_f(float x){ return 1.f/(1.f+expf(-x)); }

__device__ __forceinline__ void split1(float v, bf* H, bf* L){
  bf h = __float2bfloat16(v);
  *H = h; *L = __float2bfloat16(v - __bfloat162float(h));
}
__device__ __forceinline__ bf2 split2(float v0, float v1, bf2* lo){
  bf h0=__float2bfloat16(v0), h1=__float2bfloat16(v1);
  *lo = __halves2bfloat162(__float2bfloat16(v0-__bfloat162float(h0)),
                           __float2bfloat16(v1-__bfloat162float(h1)));
  return __halves2bfloat162(h0,h1);
}
__device__ __forceinline__ unsigned bits2(bf2 v){ return *(unsigned*)&v; }

__device__ __forceinline__ unsigned sptr(const void* p){
  return (unsigned)__cvta_generic_to_shared(p);
}
__device__ __forceinline__ void ldsm4(unsigned addr, unsigned* r){
  asm volatile("ldmatrix.sync.aligned.m8n8.x4.shared.b16 {%0,%1,%2,%3}, [%4];"
    : "=r"(r[0]),"=r"(r[1]),"=r"(r[2]),"=r"(r[3]) : "r"(addr));
}
__device__ __forceinline__ void ldsm4t(unsigned addr, unsigned* r){
  asm volatile("ldmatrix.sync.aligned.m8n8.x4.trans.shared.b16 {%0,%1,%2,%3}, [%4];"
    : "=r"(r[0]),"=r"(r[1]),"=r"(r[2]),"=r"(r[3]) : "r"(addr));
}
__device__ __forceinline__ void mmab(float* c, const unsigned* a, unsigned b0, unsigned b1){
  asm volatile("mma.sync.aligned.m16n8k16.row.col.f32.bf16.bf16.f32 "
    "{%0,%1,%2,%3},{%4,%5,%6,%7},{%8,%9},{%0,%1,%2,%3};"
    : "+f"(c[0]),"+f"(c[1]),"+f"(c[2]),"+f"(c[3])
    : "r"(a[0]),"r"(a[1]),"r"(a[2]),"r"(a[3]),"r"(b0),"r"(b1));
}
__device__ __forceinline__ void cpa16(unsigned dst, const void* src){
  asm volatile("cp.async.cg.shared.global [%0], [%1], 16;" :: "r"(dst), "l"(src));
}
#define CPCOMMIT() asm volatile("cp.async.commit_group;")
#define CPWAIT(n)  asm volatile("cp.async.wait_group %0;" :: "n"(n))

__device__ __forceinline__ float warp_sum(float s){
#pragma unroll
  for(int o=16;o>0;o>>=1) s += __shfl_xor_sync(0xffffffffu, s, o);
  return s;
}

// ---------- device-wide barrier (all 256 blocks co-resident) ----------
__device__ __forceinline__ void gsync(unsigned bar){
  unsigned target = bar*256u;
  __syncthreads();
  if(threadIdx.x==0){
    __threadfence();
    atomicAdd(&g_arrive, 1u);
    while(*((volatile unsigned*)&g_arrive) < target) __nanosleep(64);
    __threadfence();
  }
  __syncthreads();
}

// ---------- cp.async tile loaders ----------
template<int ROWS>
__device__ __forceinline__ void cp_nat(const bf* __restrict__ Gh, const bf* __restrict__ Gl,
                                       size_t base, int ldg, int k0,
                                       bf* Sh, bf* Sl, int tid){
  if(2*ROWS>=256 || tid < 2*ROWS){
    int r = tid>>1, q = (tid&1)<<3;
    size_t off = base + (size_t)r*ldg + k0 + q;
    cpa16(sptr(Sh + r*24 + q), Gh + off);
    cpa16(sptr(Sl + r*24 + q), Gl + off);
  }
}
template<int COLS,int SSTR>
__device__ __forceinline__ void cp_trans(const bf* __restrict__ Gh, const bf* __restrict__ Gl,
                                         size_t base, int ldg, int k0, int n0,
                                         bf* Sh, bf* Sl, int tid){
  constexpr int CPT = COLS/8;
  if(16*CPT>=256 || tid < 16*CPT){
    int r = tid/CPT, c = (tid%CPT)<<3;
    size_t off = base + (size_t)(k0+r)*ldg + n0 + c;
    cpa16(sptr(Sh + r*SSTR + c), Gh + off);
    cpa16(sptr(Sl + r*SSTR + c), Gl + off);
  }
}

// ---------- one k16 bf16x3 mma stage ----------
template<int MT,int PN,bool AT,int ASTR,bool BT,int BSTR>
__device__ __forceinline__ void mma_stageP(const bf* AhS, const bf* AlS,
                                           const bf* BhS, const bf* BlS,
                                           float (*acc)[2*PN][4], int wm,int wn,int lane){
  unsigned ah[MT][4], al[MT][4];
#pragma unroll
  for(int mt=0;mt<MT;mt++){
    if(!AT){
      int r = wm*(MT*16)+mt*16 + (lane&15);
      int c = (lane&16)>>1;
      ldsm4 (sptr(AhS + r*ASTR + c), ah[mt]);
      ldsm4 (sptr(AlS + r*ASTR + c), al[mt]);
    }else{
      int r = (lane&7) + ((lane&16)>>1);
      int c = wm*(MT*16)+mt*16 + (lane&8);
      ldsm4t(sptr(AhS + r*ASTR + c), ah[mt]);
      ldsm4t(sptr(AlS + r*ASTR + c), al[mt]);
    }
  }
#pragma unroll
  for(int p=0;p<PN;p++){
    unsigned bh[4], bl[4];
    if(!BT){
      int r = wn*(PN*16)+p*16 + (lane&7) + ((lane>>1)&8);
      int c = lane&8;
      ldsm4 (sptr(BhS + r*BSTR + c), bh);
      ldsm4 (sptr(BlS + r*BSTR + c), bl);
    }else{
      int r = (lane&7) + (lane&8);
      int c = wn*(PN*16)+p*16 + ((lane&16)>>1);
      ldsm4t(sptr(BhS + r*BSTR + c), bh);
      ldsm4t(sptr(BlS + r*BSTR + c), bl);
    }
#pragma unroll
    for(int mt=0;mt<MT;mt++){
      mmab(acc[mt][2*p  ], ah[mt], bh[0],bh[1]);
      mmab(acc[mt][2*p  ], al[mt], bh[0],bh[1]);
      mmab(acc[mt][2*p  ], ah[mt], bl[0],bl[1]);
      mmab(acc[mt][2*p+1], ah[mt], bh[2],bh[3]);
      mmab(acc[mt][2*p+1], al[mt], bh[2],bh[3]);
      mmab(acc[mt][2*p+1], ah[mt], bl[2],bl[3]);
    }
  }
}

#define THREAD_IDS \
  int tid=threadIdx.x, lane=tid&31, wid=tid>>5, wm=wid>>1, wn=wid&1; \
  int gid=lane>>2, tig=lane&3; (void)gid; (void)tig;

// ----------------- build (separate first launch; resets barrier) -----------
__global__ void build_all(const float* __restrict__ xs, const float* __restrict__ ys,
                          const float* __restrict__ qx,
                          const float* __restrict__ Wq, const float* __restrict__ Wk,
                          const float* __restrict__ Wv, const float* __restrict__ Wg,
                          const float* __restrict__ Wo,
                          const float* __restrict__ l1w, const float* __restrict__ l1b){
  int bid = blockIdx.x;
  if(bid==0 && threadIdx.x==0) g_arrive = 0u;
  if(bid < 1024){
    int warp = threadIdx.x>>5, lane = threadIdx.x&31;
    int tok = bid*8 + warp;
    int b = tok>>12, t = tok&4095;
    float v[4];
#pragma unroll
    for(int j=0;j<4;j++){
      int d = lane*4 + j;
      if(t < 4095) v[j] = (d<127) ? xs[((size_t)b*4095+t)*127+d] : ys[(size_t)b*4095+t];
      else         v[j] = (d<127) ? qx[(size_t)b*127+d] : 0.f;
    }
    size_t idx = (size_t)tok*128 + lane*4;
    *(float4*)&g_tokens[idx] = make_float4(v[0],v[1],v[2],v[3]);
    float s = warp_sum(v[0]+v[1]+v[2]+v[3]);
    float q = warp_sum(v[0]*v[0]+v[1]*v[1]+v[2]*v[2]+v[3]*v[3]);
    float m = s*(1.f/128.f);
    float inv = rsqrtf(q*(1.f/128.f) - m*m + 1e-5f);
    float4 wv = *(const float4*)&l1w[lane*4];
    float4 bv = *(const float4*)&l1b[lane*4];
    float o0=(v[0]-m)*inv*wv.x+bv.x, o1=(v[1]-m)*inv*wv.y+bv.y;
    float o2=(v[2]-m)*inv*wv.z+bv.z, o3=(v[3]-m)*inv*wv.w+bv.w;
    bf2 l0,l1_; bf2 h0=split2(o0,o1,&l0), h1=split2(o2,o3,&l1_);
    *(uint2*)&g_x_h[idx] = make_uint2(bits2(h0), bits2(h1));
    *(uint2*)&g_x_l[idx] = make_uint2(bits2(l0), bits2(l1_));
  }else if(bid < 1536){
    int idx = (bid-1024)*256 + threadIdx.x;
    int l = idx >> 16;
    int r = idx & ((1<<16)-1);
    int n = r >> 7, k = r & 127;
    float v = 0.f;
    if(n < 127)        v = Wq[((size_t)l*127 + n)*128 + k];
    else if(n == 127)  v = 0.f;
    else if(n < 255)   v = Wk[((size_t)l*127 + (n-128))*128 + k];
    else if(n == 255)  v = 0.f;
    else if(n < 384)   v = Wv[((size_t)l*128 + (n-256))*128 + k];
    else               v = Wg[((size_t)l*128 + (n-384))*128 + k];
    split1(v, &g_Wc_h[idx], &g_Wc_l[idx]);
  }else{
    int idx = (bid-1536)*256 + threadIdx.x;
    split1(Wo[idx], &g_Wo_h[idx], &g_Wo_l[idx]);
  }
}

// ================= phase functions ==========================================
__device__ void proj_phase(int vb, char* SB, int l, const float* __restrict__ gb){
  THREAD_IDS;
  if(vb < 128){
    bf* Ahp=(bf*)SB; bf* Alp=(bf*)(SB+12288);
    bf* Bhp=(bf*)(SB+24576); bf* Blp=(bf*)(SB+36864);
    float acc[2][8][4];
#pragma unroll
    for(int i=0;i<2;i++)
#pragma unroll
      for(int j=0;j<8;j++)
#pragma unroll
        for(int k=0;k<4;k++) acc[i][j][k]=0.f;
    int y = vb>>6, xb = vb&63;
    size_t abase = (size_t)xb*128*128;
    size_t bbase = ((size_t)l*512 + y*128)*128;
    cp_nat<128>(g_x_h, g_x_l, abase, 128, 0, Ahp, Alp, tid);
    cp_nat<128>(g_Wc_h,g_Wc_l,bbase, 128, 0, Bhp, Blp, tid);
    CPCOMMIT();
    for(int s=0;s<8;s++){
      CPWAIT(0);
      __syncthreads();
      if(s<7){
        int nb=(s+1)&1;
        cp_nat<128>(g_x_h, g_x_l, abase, 128, (s+1)*16, Ahp+nb*3072, Alp+nb*3072, tid);
        cp_nat<128>(g_Wc_h,g_Wc_l,bbase, 128, (s+1)*16, Bhp+nb*3072, Blp+nb*3072, tid);
        CPCOMMIT();
      }
      int cb=s&1;
      mma_stageP<2,4,false,24,false,24>(Ahp+cb*3072,Alp+cb*3072,Bhp+cb*3072,Blp+cb*3072,acc,wm,wn,lane);
    }
    bf* Dh = y ? g_Kp_h : g_Qp_h;
    bf* Dl = y ? g_Kp_l : g_Qp_l;
    float sc[16];
#pragma unroll
    for(int j=0;j<16;j++) sc[j]=0.f;
#pragma unroll
    for(int mt=0;mt<2;mt++){
      int r0 = wm*32+mt*16+gid;
#pragma unroll
      for(int nt=0;nt<8;nt++){
        int col = wn*64+nt*8+tig*2;
        float* a = acc[mt][nt];
        float v0 = (col  <127)? phi_f(a[0]) : 0.f;
        float v1 = (col+1<127)? phi_f(a[1]) : 0.f;
        float v2 = (col  <127)? phi_f(a[2]) : 0.f;
        float v3 = (col+1<127)? phi_f(a[3]) : 0.f;
        sc[2*nt] += v0+v2; sc[2*nt+1] += v1+v3;
        bf2 lo;
        bf2 hi = split2(v0,v1,&lo);
        *(bf2*)&Dh[abase + (size_t)r0*128+col] = hi;
        *(bf2*)&Dl[abase + (size_t)r0*128+col] = lo;
        hi = split2(v2,v3,&lo);
        *(bf2*)&Dh[abase + (size_t)(r0+8)*128+col] = hi;
        *(bf2*)&Dl[abase + (size_t)(r0+8)*128+col] = lo;
      }
    }
    if(y==1){
#pragma unroll
      for(int j=0;j<16;j++){
        sc[j] += __shfl_xor_sync(0xffffffffu, sc[j], 4);
        sc[j] += __shfl_xor_sync(0xffffffffu, sc[j], 8);
        sc[j] += __shfl_xor_sync(0xffffffffu, sc[j], 16);
      }
      __syncthreads();
      float (*KsP)[128] = (float(*)[128])SB;
      if(lane<4){
#pragma unroll
        for(int j=0;j<16;j++){
          int col = wn*64 + (j>>1)*8 + lane*2 + (j&1);
          KsP[wm][col] = sc[j];
        }
      }
      __syncthreads();
      if(tid<128)
        g_Ksum[(size_t)xb*128 + tid] = KsP[0][tid]+KsP[1][tid]+KsP[2][tid]+KsP[3][tid];
    }
  }else{
    bf* Ahp=(bf*)SB; bf* Alp=(bf*)(SB+6144);
    bf* Bhp=(bf*)(SB+12288); bf* Blp=(bf*)(SB+24576);
    float accV[1][8][4], accG[1][8][4];
#pragma unroll
    for(int j=0;j<8;j++)
#pragma unroll
      for(int k=0;k<4;k++){ accV[0][j][k]=0.f; accG[0][j][k]=0.f; }
    int xb = vb - 128;
    size_t abase  = (size_t)xb*64*128;
    size_t bbaseV = ((size_t)l*512 + 256)*128;
    size_t bbaseG = ((size_t)l*512 + 384)*128;
    cp_nat<64> (g_x_h, g_x_l, abase,  128, 0, Ahp, Alp, tid);
    cp_nat<128>(g_Wc_h,g_Wc_l,bbaseV, 128, 0, Bhp, Blp, tid);
    CPCOMMIT();
    for(int s=0;s<16;s++){
      CPWAIT(0);
      __syncthreads();
      if(s<15){
        int s1=s+1, nb=s1&1;
        size_t bb = (s1<8)? bbaseV : bbaseG;
        cp_nat<64> (g_x_h, g_x_l, abase, 128, (s1&7)*16, Ahp+nb*1536, Alp+nb*1536, tid);
        cp_nat<128>(g_Wc_h,g_Wc_l,bb,    128, (s1&7)*16, Bhp+nb*3072, Blp+nb*3072, tid);
        CPCOMMIT();
      }
      int cb=s&1;
      float (*ac)[8][4] = (s<8)? accV : accG;
      mma_stageP<1,4,false,24,false,24>(Ahp+cb*1536,Alp+cb*1536,Bhp+cb*3072,Blp+cb*3072,ac,wm,wn,lane);
    }
    int r0 = wm*16+gid;
#pragma unroll
    for(int nt=0;nt<8;nt++){
      int col = wn*64+nt*8+tig*2;
      float* v = accV[0][nt];
      float* g = accG[0][nt];
      float gb0 = gb[col], gb1 = gb[col+1];
      float o0 = v[0]*sigm_f(g[0]+gb0), o1 = v[1]*sigm_f(g[1]+gb1);
      float o2 = v[2]*sigm_f(g[2]+gb0), o3 = v[3]*sigm_f(g[3]+gb1);
      bf2 lo;
      bf2 hi = split2(o0,o1,&lo);
      *(bf2*)&g_Vg_h[abase + (size_t)r0*128+col] = hi;
      *(bf2*)&g_Vg_l[abase + (size_t)r0*128+col] = lo;
      hi = split2(o2,o3,&lo);
      *(bf2*)&g_Vg_h[abase + (size_t)(r0+8)*128+col] = hi;
      *(bf2*)&g_Vg_l[abase + (size_t)(r0+8)*128+col] = lo;
    }
  }
}

// chunk1: vb<128 -> KV 64-col slices (triple-buffered); vb>=128 -> score 64-col halves
__device__ void chunk1_phase(int vb, char* SB){
  THREAD_IDS;
  if(vb < 128){
    int c = vb & 31, b = (vb>>5)&1, z = vb>>6;
    size_t base = ((size_t)b*TT + c*128)*128;
    bf* Ah=(bf*)SB;            bf* Al=(bf*)(SB+13056);
    bf* Bh=(bf*)(SB+26112);    bf* Bl=(bf*)(SB+33024);
    float acc[2][4][4];
#pragma unroll
    for(int i=0;i<2;i++)
#pragma unroll
      for(int j=0;j<4;j++)
#pragma unroll
        for(int k=0;k<4;k++) acc[i][j][k]=0.f;
    int n0 = z*64;
#define KV_ISSUE(s) { \
      cp_trans<128,136>(g_Kp_h,g_Kp_l, base,128,(s)*16, 0,  Ah+((s)%3)*2176, Al+((s)%3)*2176, tid); \
      cp_trans<64, 72>(g_Vg_h,g_Vg_l, base,128,(s)*16, n0, Bh+((s)%3)*1152, Bl+((s)%3)*1152, tid); \
      CPCOMMIT(); }
    KV_ISSUE(0); KV_ISSUE(1);
    for(int s=0;s<8;s++){
      if(s<7) CPWAIT(1); else CPWAIT(0);
      __syncthreads();
      if(s+2<8) KV_ISSUE(s+2);
      int cb=s%3;
      mma_stageP<2,2,true,136,true,72>(Ah+cb*2176,Al+cb*2176,Bh+cb*1152,Bl+cb*1152,acc,wm,wn,lane);
    }
#undef KV_ISSUE
    float* C = g_KV + (size_t)(b*NC + c)*16384 + n0;
#pragma unroll
    for(int mt=0;mt<2;mt++){
      int r0 = wm*32+mt*16+gid;
#pragma unroll
      for(int nt=0;nt<4;nt++){
        int col = wn*32+nt*8+tig*2;
        float* a = acc[mt][nt];
        *(float2*)&C[(size_t)r0*128+col]     = make_float2(a[0],a[1]);
        *(float2*)&C[(size_t)(r0+8)*128+col] = make_float2(a[2],a[3]);
      }
    }
  }else{
    int r = vb - 128;
    int c = r & 31, b = (r>>5)&1, zz = r>>6;
    size_t base = ((size_t)b*TT + c*128)*128;
    bf* Ahp=(bf*)SB;            bf* Alp=(bf*)(SB+12288);
    bf* Bhp=(bf*)(SB+24576);    bf* Blp=(bf*)(SB+30720);
    float (*rs2s)[2] = (float(*)[2])(SB+36864);
    float acc[2][4][4];
#pragma unroll
    for(int i=0;i<2;i++)
#pragma unroll
      for(int j=0;j<4;j++)
#pragma unroll
        for(int k=0;k<4;k++) acc[i][j][k]=0.f;
    size_t bbase = base + (size_t)(zz*64)*128;
    cp_nat<128>(g_Qp_h,g_Qp_l, base, 128, 0, Ahp, Alp, tid);
    cp_nat<64> (g_Kp_h,g_Kp_l, bbase,128, 0, Bhp, Blp, tid);
    CPCOMMIT();
    for(int s=0;s<8;s++){
      CPWAIT(0);
      __syncthreads();
      if(s<7){
        int nb=(s+1)&1;
        cp_nat<128>(g_Qp_h,g_Qp_l, base, 128,(s+1)*16, Ahp+nb*3072, Alp+nb*3072, tid);
        cp_nat<64> (g_Kp_h,g_Kp_l, bbase,128,(s+1)*16, Bhp+nb*1536, Blp+nb*1536, tid);
        CPCOMMIT();
      }
      int cb=s&1;
      mma_stageP<2,2,false,24,false,24>(Ahp+cb*3072,Alp+cb*3072,Bhp+cb*1536,Blp+cb*1536,acc,wm,wn,lane);
    }
#pragma unroll
    for(int mt=0;mt<2;mt++){
      int r0 = wm*32+mt*16+gid;
      float s0=0.f, s1=0.f;
#pragma unroll
      for(int nt=0;nt<4;nt++){
        int col = zz*64 + wn*32 + nt*8 + tig*2;
        float* a = acc[mt][nt];
        float v0 = (col   <= r0  )? a[0] : 0.f;
        float v1 = (col+1 <= r0  )? a[1] : 0.f;
        float v2 = (col   <= r0+8)? a[2] : 0.f;
        float v3 = (col+1 <= r0+8)? a[3] : 0.f;
        s0 += v0+v1; s1 += v2+v3;
        bf2 lo;
        bf2 hi = split2(v0,v1,&lo);
        *(bf2*)&g_As_h[base + (size_t)r0*128+col] = hi;
        *(bf2*)&g_As_l[base + (size_t)r0*128+col] = lo;
        hi = split2(v2,v3,&lo);
        *(bf2*)&g_As_h[base + (size_t)(r0+8)*128+col] = hi;
        *(bf2*)&g_As_l[base + (size_t)(r0+8)*128+col] = lo;
      }
      s0 += __shfl_xor_sync(0xffffffffu, s0, 1); s0 += __shfl_xor_sync(0xffffffffu, s0, 2);
      s1 += __shfl_xor_sync(0xffffffffu, s1, 1); s1 += __shfl_xor_sync(0xffffffffu, s1, 2);
      if(tig==0){ rs2s[r0][wn]=s0; rs2s[r0+8][wn]=s1; }
    }
    __syncthreads();
    if(tid<128)
      g_rs[((size_t)b*TT + c*128 + tid)*2 + zz] = rs2s[tid][0] + rs2s[tid][1];
  }
}

__device__ void scan_phase(int vb, char* SB){
  float4 (*gt)[32] = (float4(*)[32])SB;
  int h = vb & 127, b = vb >> 7;
  int q = threadIdx.x & 31, g = threadIdx.x >> 5;
  size_t rowbase = (((size_t)b*NC)*128 + h)*128 + q*4;
  float4 v[4], pre[4];
#pragma unroll
  for(int j=0;j<4;j++) v[j] = *(const float4*)&g_KV[rowbase + (size_t)(g*4+j)*16384];
  float4 loc = make_float4(0.f,0.f,0.f,0.f);
#pragma unroll
  for(int j=0;j<4;j++){
    pre[j] = loc;
    loc.x += v[j].x; loc.y += v[j].y; loc.z += v[j].z; loc.w += v[j].w;
  }
  gt[g][q] = loc;
  __syncthreads();
  float4 off = make_float4(0.f,0.f,0.f,0.f);
#pragma unroll
  for(int gg=0;gg<7;gg++) if(gg < g){
    float4 t = gt[gg][q];
    off.x += t.x; off.y += t.y; off.z += t.z; off.w += t.w;
  }
#pragma unroll
  for(int j=0;j<4;j++){
    size_t i = rowbase + (size_t)(g*4+j)*16384;
    float a0 = off.x + pre[j].x, a1 = off.y + pre[j].y;
    float a2 = off.z + pre[j].z, a3 = off.w + pre[j].w;
    bf2 lo0, lo1;
    bf2 hi0 = split2(a0, a1, &lo0);
    bf2 hi1 = split2(a2, a3, &lo1);
    *(uint2*)&g_S_h[i] = make_uint2(bits2(hi0), bits2(hi1));
    *(uint2*)&g_S_l[i] = make_uint2(bits2(lo0), bits2(lo1));
  }
  if(threadIdx.x < NC){
    int mm = threadIdx.x;
    float ks = g_Ksum[(size_t)(b*NC + mm)*128 + h];
    float x = ks;
#pragma unroll
    for(int o=1;o<NC;o<<=1){
      float y = __shfl_up_sync(0xffffffffu, x, o);
      if(mm>=o) x += y;
    }
    g_KsumX[(size_t)(b*NC + mm)*128 + h] = x - ks;
  }
}

__device__ void num_phase(int vb, char* SB){
  bf* Ah=(bf*)SB;          bf* Al=(bf*)(SB+18432);
  bf* Bh=(bf*)(SB+36864);  bf* Bl=(bf*)(SB+40704);
  float* kx  = (float*)(SB+44544);
  float* dsm = (float*)(SB+45056);
  THREAD_IDS;
  int c = vb & 31, b = (vb>>5)&1, z = vb>>6;
  int n0 = z*32;
  size_t base  = ((size_t)b*TT + c*128)*128;
  size_t sbase = (size_t)(b*NC + c)*16384;
  float acc[2][2][4];
#pragma unroll
  for(int i=0;i<2;i++)
#pragma unroll
    for(int j=0;j<2;j++)
#pragma unroll
      for(int k=0;k<4;k++) acc[i][j][k]=0.f;
  if(tid<128) kx[tid] = g_KsumX[(size_t)(b*NC + c)*128 + tid];
  float dd = 0.f;
#define NUM_ISSUE(s) { \
    if((s)<8){ \
      cp_nat<128>   (g_As_h,g_As_l, base,128,(s)*16,     Ah+((s)%3)*3072, Al+((s)%3)*3072, tid); \
      cp_trans<32,40>(g_Vg_h,g_Vg_l, base,128,(s)*16, n0, Bh+((s)%3)*640,  Bl+((s)%3)*640,  tid); \
    }else{ \
      cp_nat<128>   (g_Qp_h,g_Qp_l, base, 128,((s)-8)*16,     Ah+((s)%3)*3072, Al+((s)%3)*3072, tid); \
      cp_trans<32,40>(g_S_h, g_S_l, sbase,128,((s)-8)*16, n0, Bh+((s)%3)*640,  Bl+((s)%3)*640,  tid); \
    } \
    CPCOMMIT(); }
  NUM_ISSUE(0); NUM_ISSUE(1);
  for(int s=0;s<16;s++){
    if(s<15) CPWAIT(1); else CPWAIT(0);
    __syncthreads();
    if(s+2<16) NUM_ISSUE(s+2);
    int cb=s%3;
    mma_stageP<2,1,false,24,true,40>(Ah+cb*3072,Al+cb*3072,Bh+cb*640,Bl+cb*640,acc,wm,wn,lane);
    if(s>=8 && tid<128){
      const bf* ac  = Ah + cb*3072 + tid*24;
      const bf* alc = Al + cb*3072 + tid*24;
      int kb = (s-8)*16;
#pragma unroll
      for(int k=0;k<16;k++)
        dd += (__bfloat162float(ac[k])+__bfloat162float(alc[k])) * kx[kb+k];
    }
  }
#undef NUM_ISSUE
  if(tid<128){
    size_t bt2 = ((size_t)b*TT + c*128 + tid)*2;
    dsm[tid] = fmaxf(g_rs[bt2] + g_rs[bt2+1] + dd, 1e-6f);
  }
  __syncthreads();
#pragma unroll
  for(int mt=0;mt<2;mt++){
    int r0 = wm*32+mt*16+gid;
    float inv0 = 1.f/dsm[r0], inv1 = 1.f/dsm[r0+8];
#pragma unroll
    for(int nt=0;nt<2;nt++){
      int col = n0 + wn*16 + nt*8 + tig*2;
      float* a = acc[mt][nt];
      bf2 lo;
      bf2 hi = split2(a[0]*inv0, a[1]*inv0, &lo);
      *(bf2*)&g_at_h[base + (size_t)r0*128+col] = hi;
      *(bf2*)&g_at_l[base + (size_t)r0*128+col] = lo;
      hi = split2(a[2]*inv1, a[3]*inv1, &lo);
      *(bf2*)&g_at_h[base + (size_t)(r0+8)*128+col] = hi;
      *(bf2*)&g_at_l[base + (size_t)(r0+8)*128+col] = lo;
    }
  }
}

// wo: 128 blocks of 64 rows (R13 shape). Last layer: (vb&63)==63 -> pred.
__device__ void wo_phase(int vb, char* SB, int l,
                         const float* __restrict__ w2, const float* __restrict__ b2,
                         const float* __restrict__ w1, const float* __restrict__ b1,
                         int do_ln1, const float* __restrict__ pw, float* __restrict__ out){
  bf* Ahp=(bf*)SB;          bf* Alp=(bf*)(SB+6144);
  bf* Bhp=(bf*)(SB+12288);  bf* Blp=(bf*)(SB+24576);
  float (*Ps)[8] = (float(*)[8])(SB+36864);
  float (*Qs)[8] = (float(*)[8])(SB+38912);
  float* Mu = (float*)(SB+40960);
  float* Rv = (float*)(SB+41216);
  float* rr2 = (float*)(SB+41472);
  THREAD_IDS;
  float acc[1][8][4];
#pragma unroll
  for(int j=0;j<8;j++)
#pragma unroll
    for(int k=0;k<4;k++) acc[0][j][k]=0.f;
  size_t abase = (size_t)vb*64*128;
  size_t bbase = (size_t)l*16384;
  cp_nat<64> (g_at_h,g_at_l, abase,128, 0, Ahp, Alp, tid);
  cp_nat<128>(g_Wo_h,g_Wo_l, bbase,128, 0, Bhp, Blp, tid);
  CPCOMMIT();
  for(int s=0;s<8;s++){
    CPWAIT(0);
    __syncthreads();
    if(s<7){
      int nb=(s+1)&1;
      cp_nat<64> (g_at_h,g_at_l, abase,128,(s+1)*16, Ahp+nb*1536, Alp+nb*1536, tid);
      cp_nat<128>(g_Wo_h,g_Wo_l, bbase,128,(s+1)*16, Bhp+nb*3072, Blp+nb*3072, tid);
      CPCOMMIT();
    }
    int cb=s&1;
    mma_stageP<1,4,false,24,false,24>(Ahp+cb*1536,Alp+cb*1536,Bhp+cb*3072,Blp+cb*3072,acc,wm,wn,lane);
  }
  int slot = wn*4 + tig;
  size_t row0 = (size_t)vb*64;
  int rl0 = wm*16+gid;
  {
    float s0=0.f,q0=0.f,s1=0.f,q1=0.f;
#pragma unroll
    for(int nt=0;nt<8;nt++){
      int col = wn*64+nt*8+tig*2;
      float* a = acc[0][nt];
      float x0 = g_tokens[(row0+rl0)*128+col  ] + 0.1f*a[0];
      float x1 = g_tokens[(row0+rl0)*128+col+1] + 0.1f*a[1];
      float x2 = g_tokens[(row0+rl0+8)*128+col  ] + 0.1f*a[2];
      float x3 = g_tokens[(row0+rl0+8)*128+col+1] + 0.1f*a[3];
      a[0]=x0; a[1]=x1; a[2]=x2; a[3]=x3;
      s0 += x0+x1; q0 += x0*x0+x1*x1;
      s1 += x2+x3; q1 += x2*x2+x3*x3;
    }
    Ps[rl0][slot]=s0; Qs[rl0][slot]=q0;
    Ps[rl0+8][slot]=s1; Qs[rl0+8][slot]=q1;
  }
  __syncthreads();
  if(tid < 64){
    float s=0.f,q=0.f;
#pragma unroll
    for(int j=0;j<8;j++){ s+=Ps[tid][j]; q+=Qs[tid][j]; }
    float m = s*(1.f/128.f);
    float v = q*(1.f/128.f) - m*m;
    Mu[tid]=m; Rv[tid]=rsqrtf(v + 1e-5f);
  }
  __syncthreads();
  {
    float m0=Mu[rl0], i0=Rv[rl0], m1=Mu[rl0+8], i1=Rv[rl0+8];
    float s0=0.f,q0=0.f,s1=0.f,q1=0.f;
#pragma unroll
    for(int nt=0;nt<8;nt++){
      int col = wn*64+nt*8+tig*2;
      float* a = acc[0][nt];
      float w0=w2[col], w1_=w2[col+1], bb0=b2[col], bb1=b2[col+1];
      float y0=(a[0]-m0)*i0*w0+bb0, y1=(a[1]-m0)*i0*w1_+bb1;
      float y2=(a[2]-m1)*i1*w0+bb0, y3=(a[3]-m1)*i1*w1_+bb1;
      *(float2*)&g_tokens[(row0+rl0)*128+col]   = make_float2(y0,y1);
      *(float2*)&g_tokens[(row0+rl0+8)*128+col] = make_float2(y2,y3);
      a[0]=y0; a[1]=y1; a[2]=y2; a[3]=y3;
      s0 += y0+y1; q0 += y0*y0+y1*y1;
      s1 += y2+y3; q1 += y2*y2+y3*y3;
    }
    if(do_ln1){ Ps[rl0][slot]=s0; Qs[rl0][slot]=q0; Ps[rl0+8][slot]=s1; Qs[rl0+8][slot]=q1; }
  }
  if(!do_ln1){
    if((vb & 63) == 63){
      __syncthreads();
      int bb = vb >> 6;
      float v = 0.f;
      if(tid < 128) v = g_tokens[((size_t)bb*TT + (TT-1))*128 + tid] * pw[tid];
#pragma unroll
      for(int o=16;o>0;o>>=1) v += __shfl_down_sync(0xffffffffu, v, o);
      if(lane==0) rr2[wid]=v;
      __syncthreads();
      if(tid==0){
        float s=0.f;
#pragma unroll
        for(int j=0;j<8;j++) s+=rr2[j];
        out[bb] = s;
      }
    }
    return;
  }
  __syncthreads();
  if(tid < 64){
    float s=0.f,q=0.f;
#pragma unroll
    for(int j=0;j<8;j++){ s+=Ps[tid][j]; q+=Qs[tid][j]; }
    float m = s*(1.f/128.f);
    float v = q*(1.f/128.f) - m*m;
    Mu[tid]=m; Rv[tid]=rsqrtf(v + 1e-5f);
  }
  __syncthreads();
  {
    float m0=Mu[rl0], i0=Rv[rl0], m1=Mu[rl0+8], i1=Rv[rl0+8];
#pragma unroll
    for(int nt=0;nt<8;nt++){
      int col = wn*64+nt*8+tig*2;
      float* a = acc[0][nt];
      float w0=w1[col], w1_=w1[col+1], bb0=b1[col], bb1=b1[col+1];
      float y0=(a[0]-m0)*i0*w0+bb0, y1=(a[1]-m0)*i0*w1_+bb1;
      float y2=(a[2]-m1)*i1*w0+bb0, y3=(a[3]-m1)*i1*w1_+bb1;
      bf2 lo;
      bf2 hi = split2(y0,y1,&lo);
      *(bf2*)&g_x_h[(row0+rl0)*128+col] = hi;
      *(bf2*)&g_x_l[(row0+rl0)*128+col] = lo;
      hi = split2(y2,y3,&lo);
      *(bf2*)&g_x_h[(row0+rl0+8)*128+col] = hi;
      *(bf2*)&g_x_l[(row0+rl0+8)*128+col] = lo;
    }
  }
}

// ================= mega kernel: both layers, device barriers ================
__global__ void __launch_bounds__(256,2)
mega_kernel(const float* __restrict__ Wgb,
            const float* __restrict__ ln1w, const float* __restrict__ ln1b,
            const float* __restrict__ ln2w, const float* __restrict__ ln2b,
            const float* __restrict__ pw, float* __restrict__ out){
  extern __shared__ char SB[];
  int vb = blockIdx.x;
  unsigned bar = 0;
  for(int l=0;l<2;l++){
    proj_phase(vb, SB, l, Wgb + l*128);
    gsync(++bar);
    chunk1_phase(vb, SB);
    gsync(++bar);
    scan_phase(vb, SB);
    gsync(++bar);
    num_phase(vb, SB);
    gsync(++bar);
    if(vb < 128)
      wo_phase(vb, SB, l, ln2w + l*128, ln2b + l*128,
               ln1w + (l+1<2?(l+1):l)*128, ln1b + (l+1<2?(l+1):l)*128,
               l+1 < 2, pw, out);
    if(l==0) gsync(++bar);
  }
}

// ----------------- launch -----------------
extern "C" void kernel_launch(void* const* d_in, const int* in_sizes, int n_in,
                              void* d_out, int out_size){
  const float* xs   = (const float*)d_in[0];
  const float* ys   = (const float*)d_in[1];
  const float* qx   = (const float*)d_in[2];
  const float* Wq   = (const float*)d_in[3];
  const float* Wk   = (const float*)d_in[4];
  const float* Wv   = (const float*)d_in[5];
  const float* Wgw  = (const float*)d_in[6];
  const float* Wgb  = (const float*)d_in[7];
  const float* Wo   = (const float*)d_in[8];
  const float* ln1w = (const float*)d_in[9];
  const float* ln1b = (const float*)d_in[10];
  const float* ln2w = (const float*)d_in[11];
  const float* ln2b = (const float*)d_in[12];
  const float* pw   = (const float*)d_in[13];
  float* out = (float*)d_out;

  build_all<<<1664, 256>>>(xs, ys, qx, Wq, Wk, Wv, Wgw, Wo, ln1w, ln1b);
  mega_kernel<<<256, 256, 49152>>>(Wgb, ln1w, ln1b, ln2w, ln2b, pw, out);
}

// round 16
// speedup vs baseline: 1.0902x; 1.0199x over previous
#include <cuda_runtime.h>
#include <cuda_bf16.h>
#include <math.h>

#define TT 4096
#define NB 2
#define NC 32

typedef __nv_bfloat16  bf;
typedef __nv_bfloat162 bf2;

// ----------------- static device scratch -----------------
__device__ __align__(16) float g_tokens[NB*TT*128];
__device__ __align__(16) float g_KV[NB*NC*128*128];
__device__ __align__(16) float g_Ksum[NB*NC*128];
__device__ __align__(16) float g_KsumX[NB*NC*128];
__device__ __align__(16) float g_rs[NB*TT*2];

__device__ __align__(16) bf g_x_h [NB*TT*128], g_x_l [NB*TT*128];
__device__ __align__(16) bf g_Qp_h[NB*TT*128], g_Qp_l[NB*TT*128];
__device__ __align__(16) bf g_Kp_h[NB*TT*128], g_Kp_l[NB*TT*128];
__device__ __align__(16) bf g_Vg_h[NB*TT*128], g_Vg_l[NB*TT*128];
__device__ __align__(16) bf g_As_h[NB*TT*128], g_As_l[NB*TT*128];
__device__ __align__(16) bf g_S_h [NB*NC*128*128], g_S_l [NB*NC*128*128];
__device__ __align__(16) bf g_at_h[NB*TT*128], g_at_l[NB*TT*128];
__device__ __align__(16) bf g_Wc_h[2*512*128],  g_Wc_l[2*512*128];
__device__ __align__(16) bf g_Wo_h[2*128*128],  g_Wo_l[2*128*128];

__device__ unsigned g_arrive;

// ----------------- helpers -----------------
__device__ __forceinline__ float phi_f(float x){ return x > 0.f ? x + 1.f : expf(x); }
__device__ __forceinline__ float sigm_f(float x){ return 1.f/(1.f+expf(-x)); }

__device__ __forceinline__ void split1(float v, bf* H, bf* L){
  bf h = __float2bfloat16(v);
  *H = h; *L = __float2bfloat16(v - __bfloat162float(h));
}
__device__ __forceinline__ bf2 split2(float v0, float v1, bf2* lo){
  bf h0=__float2bfloat16(v0), h1=__float2bfloat16(v1);
  *lo = __halves2bfloat162(__float2bfloat16(v0-__bfloat162float(h0)),
                           __float2bfloat16(v1-__bfloat162float(h1)));
  return __halves2bfloat162(h0,h1);
}
__device__ __forceinline__ unsigned bits2(bf2 v){ return *(unsigned*)&v; }

__device__ __forceinline__ unsigned sptr(const void* p){
  return (unsigned)__cvta_generic_to_shared(p);
}
__device__ __forceinline__ void ldsm4(unsigned addr, unsigned* r){
  asm volatile("ldmatrix.sync.aligned.m8n8.x4.shared.b16 {%0,%1,%2,%3}, [%4];"
    : "=r"(r[0]),"=r"(r[1]),"=r"(r[2]),"=r"(r[3]) : "r"(addr));
}
__device__ __forceinline__ void ldsm4t(unsigned addr, unsigned* r){
  asm volatile("ldmatrix.sync.aligned.m8n8.x4.trans.shared.b16 {%0,%1,%2,%3}, [%4];"
    : "=r"(r[0]),"=r"(r[1]),"=r"(r[2]),"=r"(r[3]) : "r"(addr));
}
__device__ __forceinline__ void mmab(float* c, const unsigned* a, unsigned b0, unsigned b1){
  asm volatile("mma.sync.aligned.m16n8k16.row.col.f32.bf16.bf16.f32 "
    "{%0,%1,%2,%3},{%4,%5,%6,%7},{%8,%9},{%0,%1,%2,%3};"
    : "+f"(c[0]),"+f"(c[1]),"+f"(c[2]),"+f"(c[3])
    : "r"(a[0]),"r"(a[1]),"r"(a[2]),"r"(a[3]),"r"(b0),"r"(b1));
}
__device__ __forceinline__ void cpa16(unsigned dst, const void* src){
  asm volatile("cp.async.cg.shared.global [%0], [%1], 16;" :: "r"(dst), "l"(src));
}
#define CPCOMMIT() asm volatile("cp.async.commit_group;")
#define CPWAIT(n)  asm volatile("cp.async.wait_group %0;" :: "n"(n))

__device__ __forceinline__ float warp_sum(float s){
#pragma unroll
  for(int o=16;o>0;o>>=1) s += __shfl_xor_sync(0xffffffffu, s, o);
  return s;
}

// ---------- device-wide barrier (all 256 blocks co-resident) ----------
__device__ __forceinline__ void gsync(unsigned bar){
  unsigned target = bar*256u;
  __syncthreads();
  if(threadIdx.x==0){
    __threadfence();
    atomicAdd(&g_arrive, 1u);
    while(*((volatile unsigned*)&g_arrive) < target) __nanosleep(64);
    __threadfence();
  }
  __syncthreads();
}

// ---------- cp.async tile loaders ----------
template<int ROWS>
__device__ __forceinline__ void cp_nat(const bf* __restrict__ Gh, const bf* __restrict__ Gl,
                                       size_t base, int ldg, int k0,
                                       bf* Sh, bf* Sl, int tid){
  if(2*ROWS>=256 || tid < 2*ROWS){
    int r = tid>>1, q = (tid&1)<<3;
    size_t off = base + (size_t)r*ldg + k0 + q;
    cpa16(sptr(Sh + r*24 + q), Gh + off);
    cpa16(sptr(Sl + r*24 + q), Gl + off);
  }
}
template<int COLS,int SSTR>
__device__ __forceinline__ void cp_trans(const bf* __restrict__ Gh, const bf* __restrict__ Gl,
                                         size_t base, int ldg, int k0, int n0,
                                         bf* Sh, bf* Sl, int tid){
  constexpr int CPT = COLS/8;
  if(16*CPT>=256 || tid < 16*CPT){
    int r = tid/CPT, c = (tid%CPT)<<3;
    size_t off = base + (size_t)(k0+r)*ldg + n0 + c;
    cpa16(sptr(Sh + r*SSTR + c), Gh + off);
    cpa16(sptr(Sl + r*SSTR + c), Gl + off);
  }
}

// ---------- one k16 bf16x3 mma stage ----------
template<int MT,int PN,bool AT,int ASTR,bool BT,int BSTR>
__device__ __forceinline__ void mma_stageP(const bf* AhS, const bf* AlS,
                                           const bf* BhS, const bf* BlS,
                                           float (*acc)[2*PN][4], int wm,int wn,int lane){
  unsigned ah[MT][4], al[MT][4];
#pragma unroll
  for(int mt=0;mt<MT;mt++){
    if(!AT){
      int r = wm*(MT*16)+mt*16 + (lane&15);
      int c = (lane&16)>>1;
      ldsm4 (sptr(AhS + r*ASTR + c), ah[mt]);
      ldsm4 (sptr(AlS + r*ASTR + c), al[mt]);
    }else{
      int r = (lane&7) + ((lane&16)>>1);
      int c = wm*(MT*16)+mt*16 + (lane&8);
      ldsm4t(sptr(AhS + r*ASTR + c), ah[mt]);
      ldsm4t(sptr(AlS + r*ASTR + c), al[mt]);
    }
  }
#pragma unroll
  for(int p=0;p<PN;p++){
    unsigned bh[4], bl[4];
    if(!BT){
      int r = wn*(PN*16)+p*16 + (lane&7) + ((lane>>1)&8);
      int c = lane&8;
      ldsm4 (sptr(BhS + r*BSTR + c), bh);
      ldsm4 (sptr(BlS + r*BSTR + c), bl);
    }else{
      int r = (lane&7) + (lane&8);
      int c = wn*(PN*16)+p*16 + ((lane&16)>>1);
      ldsm4t(sptr(BhS + r*BSTR + c), bh);
      ldsm4t(sptr(BlS + r*BSTR + c), bl);
    }
#pragma unroll
    for(int mt=0;mt<MT;mt++){
      mmab(acc[mt][2*p  ], ah[mt], bh[0],bh[1]);
      mmab(acc[mt][2*p  ], al[mt], bh[0],bh[1]);
      mmab(acc[mt][2*p  ], ah[mt], bl[0],bl[1]);
      mmab(acc[mt][2*p+1], ah[mt], bh[2],bh[3]);
      mmab(acc[mt][2*p+1], al[mt], bh[2],bh[3]);
      mmab(acc[mt][2*p+1], ah[mt], bl[2],bl[3]);
    }
  }
}

#define THREAD_IDS \
  int tid=threadIdx.x, lane=tid&31, wid=tid>>5, wm=wid>>1, wn=wid&1; \
  int gid=lane>>2, tig=lane&3; (void)gid; (void)tig;

// ----------------- build (separate first launch; resets barrier) -----------
__global__ void build_all(const float* __restrict__ xs, const float* __restrict__ ys,
                          const float* __restrict__ qx,
                          const float* __restrict__ Wq, const float* __restrict__ Wk,
                          const float* __restrict__ Wv, const float* __restrict__ Wg,
                          const float* __restrict__ Wo,
                          const float* __restrict__ l1w, const float* __restrict__ l1b){
  int bid = blockIdx.x;
  if(bid==0 && threadIdx.x==0) g_arrive = 0u;
  if(bid < 1024){
    int warp = threadIdx.x>>5, lane = threadIdx.x&31;
    int tok = bid*8 + warp;
    int b = tok>>12, t = tok&4095;
    float v[4];
#pragma unroll
    for(int j=0;j<4;j++){
      int d = lane*4 + j;
      if(t < 4095) v[j] = (d<127) ? xs[((size_t)b*4095+t)*127+d] : ys[(size_t)b*4095+t];
      else         v[j] = (d<127) ? qx[(size_t)b*127+d] : 0.f;
    }
    size_t idx = (size_t)tok*128 + lane*4;
    *(float4*)&g_tokens[idx] = make_float4(v[0],v[1],v[2],v[3]);
    float s = warp_sum(v[0]+v[1]+v[2]+v[3]);
    float q = warp_sum(v[0]*v[0]+v[1]*v[1]+v[2]*v[2]+v[3]*v[3]);
    float m = s*(1.f/128.f);
    float inv = rsqrtf(q*(1.f/128.f) - m*m + 1e-5f);
    float4 wv = *(const float4*)&l1w[lane*4];
    float4 bv = *(const float4*)&l1b[lane*4];
    float o0=(v[0]-m)*inv*wv.x+bv.x, o1=(v[1]-m)*inv*wv.y+bv.y;
    float o2=(v[2]-m)*inv*wv.z+bv.z, o3=(v[3]-m)*inv*wv.w+bv.w;
    bf2 l0,l1_; bf2 h0=split2(o0,o1,&l0), h1=split2(o2,o3,&l1_);
    *(uint2*)&g_x_h[idx] = make_uint2(bits2(h0), bits2(h1));
    *(uint2*)&g_x_l[idx] = make_uint2(bits2(l0), bits2(l1_));
  }else if(bid < 1536){
    int idx = (bid-1024)*256 + threadIdx.x;
    int l = idx >> 16;
    int r = idx & ((1<<16)-1);
    int n = r >> 7, k = r & 127;
    float v = 0.f;
    if(n < 127)        v = Wq[((size_t)l*127 + n)*128 + k];
    else if(n == 127)  v = 0.f;
    else if(n < 255)   v = Wk[((size_t)l*127 + (n-128))*128 + k];
    else if(n == 255)  v = 0.f;
    else if(n < 384)   v = Wv[((size_t)l*128 + (n-256))*128 + k];
    else               v = Wg[((size_t)l*128 + (n-384))*128 + k];
    split1(v, &g_Wc_h[idx], &g_Wc_l[idx]);
  }else{
    int idx = (bid-1536)*256 + threadIdx.x;
    split1(Wo[idx], &g_Wo_h[idx], &g_Wo_l[idx]);
  }
}

// ================= phase functions ==========================================
__device__ void proj_phase(int vb, char* SB, int l, const float* __restrict__ gb){
  THREAD_IDS;
  if(vb < 128){
    bf* Ahp=(bf*)SB; bf* Alp=(bf*)(SB+12288);
    bf* Bhp=(bf*)(SB+24576); bf* Blp=(bf*)(SB+36864);
    float acc[2][8][4];
#pragma unroll
    for(int i=0;i<2;i++)
#pragma unroll
      for(int j=0;j<8;j++)
#pragma unroll
        for(int k=0;k<4;k++) acc[i][j][k]=0.f;
    int y = vb>>6, xb = vb&63;
    size_t abase = (size_t)xb*128*128;
    size_t bbase = ((size_t)l*512 + y*128)*128;
    cp_nat<128>(g_x_h, g_x_l, abase, 128, 0, Ahp, Alp, tid);
    cp_nat<128>(g_Wc_h,g_Wc_l,bbase, 128, 0, Bhp, Blp, tid);
    CPCOMMIT();
    for(int s=0;s<8;s++){
      CPWAIT(0);
      __syncthreads();
      if(s<7){
        int nb=(s+1)&1;
        cp_nat<128>(g_x_h, g_x_l, abase, 128, (s+1)*16, Ahp+nb*3072, Alp+nb*3072, tid);
        cp_nat<128>(g_Wc_h,g_Wc_l,bbase, 128, (s+1)*16, Bhp+nb*3072, Blp+nb*3072, tid);
        CPCOMMIT();
      }
      int cb=s&1;
      mma_stageP<2,4,false,24,false,24>(Ahp+cb*3072,Alp+cb*3072,Bhp+cb*3072,Blp+cb*3072,acc,wm,wn,lane);
    }
    bf* Dh = y ? g_Kp_h : g_Qp_h;
    bf* Dl = y ? g_Kp_l : g_Qp_l;
    float sc[16];
#pragma unroll
    for(int j=0;j<16;j++) sc[j]=0.f;
#pragma unroll
    for(int mt=0;mt<2;mt++){
      int r0 = wm*32+mt*16+gid;
#pragma unroll
      for(int nt=0;nt<8;nt++){
        int col = wn*64+nt*8+tig*2;
        float* a = acc[mt][nt];
        float v0 = (col  <127)? phi_f(a[0]) : 0.f;
        float v1 = (col+1<127)? phi_f(a[1]) : 0.f;
        float v2 = (col  <127)? phi_f(a[2]) : 0.f;
        float v3 = (col+1<127)? phi_f(a[3]) : 0.f;
        sc[2*nt] += v0+v2; sc[2*nt+1] += v1+v3;
        bf2 lo;
        bf2 hi = split2(v0,v1,&lo);
        *(bf2*)&Dh[abase + (size_t)r0*128+col] = hi;
        *(bf2*)&Dl[abase + (size_t)r0*128+col] = lo;
        hi = split2(v2,v3,&lo);
        *(bf2*)&Dh[abase + (size_t)(r0+8)*128+col] = hi;
        *(bf2*)&Dl[abase + (size_t)(r0+8)*128+col] = lo;
      }
    }
    if(y==1){
#pragma unroll
      for(int j=0;j<16;j++){
        sc[j] += __shfl_xor_sync(0xffffffffu, sc[j], 4);
        sc[j] += __shfl_xor_sync(0xffffffffu, sc[j], 8);
        sc[j] += __shfl_xor_sync(0xffffffffu, sc[j], 16);
      }
      __syncthreads();
      float (*KsP)[128] = (float(*)[128])SB;
      if(lane<4){
#pragma unroll
        for(int j=0;j<16;j++){
          int col = wn*64 + (j>>1)*8 + lane*2 + (j&1);
          KsP[wm][col] = sc[j];
        }
      }
      __syncthreads();
      if(tid<128)
        g_Ksum[(size_t)xb*128 + tid] = KsP[0][tid]+KsP[1][tid]+KsP[2][tid]+KsP[3][tid];
    }
  }else{
    bf* Ahp=(bf*)SB; bf* Alp=(bf*)(SB+6144);
    bf* Bhp=(bf*)(SB+12288); bf* Blp=(bf*)(SB+24576);
    float accV[1][8][4], accG[1][8][4];
#pragma unroll
    for(int j=0;j<8;j++)
#pragma unroll
      for(int k=0;k<4;k++){ accV[0][j][k]=0.f; accG[0][j][k]=0.f; }
    int xb = vb - 128;
    size_t abase  = (size_t)xb*64*128;
    size_t bbaseV = ((size_t)l*512 + 256)*128;
    size_t bbaseG = ((size_t)l*512 + 384)*128;
    cp_nat<64> (g_x_h, g_x_l, abase,  128, 0, Ahp, Alp, tid);
    cp_nat<128>(g_Wc_h,g_Wc_l,bbaseV, 128, 0, Bhp, Blp, tid);
    CPCOMMIT();
    for(int s=0;s<16;s++){
      CPWAIT(0);
      __syncthreads();
      if(s<15){
        int s1=s+1, nb=s1&1;
        size_t bb = (s1<8)? bbaseV : bbaseG;
        cp_nat<64> (g_x_h, g_x_l, abase, 128, (s1&7)*16, Ahp+nb*1536, Alp+nb*1536, tid);
        cp_nat<128>(g_Wc_h,g_Wc_l,bb,    128, (s1&7)*16, Bhp+nb*3072, Blp+nb*3072, tid);
        CPCOMMIT();
      }
      int cb=s&1;
      float (*ac)[8][4] = (s<8)? accV : accG;
      mma_stageP<1,4,false,24,false,24>(Ahp+cb*1536,Alp+cb*1536,Bhp+cb*3072,Blp+cb*3072,ac,wm,wn,lane);
    }
    int r0 = wm*16+gid;
#pragma unroll
    for(int nt=0;nt<8;nt++){
      int col = wn*64+nt*8+tig*2;
      float* v = accV[0][nt];
      float* g = accG[0][nt];
      float gb0 = gb[col], gb1 = gb[col+1];
      float o0 = v[0]*sigm_f(g[0]+gb0), o1 = v[1]*sigm_f(g[1]+gb1);
      float o2 = v[2]*sigm_f(g[2]+gb0), o3 = v[3]*sigm_f(g[3]+gb1);
      bf2 lo;
      bf2 hi = split2(o0,o1,&lo);
      *(bf2*)&g_Vg_h[abase + (size_t)r0*128+col] = hi;
      *(bf2*)&g_Vg_l[abase + (size_t)r0*128+col] = lo;
      hi = split2(o2,o3,&lo);
      *(bf2*)&g_Vg_h[abase + (size_t)(r0+8)*128+col] = hi;
      *(bf2*)&g_Vg_l[abase + (size_t)(r0+8)*128+col] = lo;
    }
  }
}

// chunk1: vb<128 -> KV 64-col slices (triple-buffered); vb>=128 -> score 64-col halves
__device__ void chunk1_phase(int vb, char* SB){
  THREAD_IDS;
  if(vb < 128){
    int c = vb & 31, b = (vb>>5)&1, z = vb>>6;
    size_t base = ((size_t)b*TT + c*128)*128;
    bf* Ah=(bf*)SB;            bf* Al=(bf*)(SB+13056);
    bf* Bh=(bf*)(SB+26112);    bf* Bl=(bf*)(SB+33024);
    float acc[2][4][4];
#pragma unroll
    for(int i=0;i<2;i++)
#pragma unroll
      for(int j=0;j<4;j++)
#pragma unroll
        for(int k=0;k<4;k++) acc[i][j][k]=0.f;
    int n0 = z*64;
#define KV_ISSUE(s) { \
      cp_trans<128,136>(g_Kp_h,g_Kp_l, base,128,(s)*16, 0,  Ah+((s)%3)*2176, Al+((s)%3)*2176, tid); \
      cp_trans<64, 72>(g_Vg_h,g_Vg_l, base,128,(s)*16, n0, Bh+((s)%3)*1152, Bl+((s)%3)*1152, tid); \
      CPCOMMIT(); }
    KV_ISSUE(0); KV_ISSUE(1);
    for(int s=0;s<8;s++){
      if(s<7) CPWAIT(1); else CPWAIT(0);
      __syncthreads();
      if(s+2<8) KV_ISSUE(s+2);
      int cb=s%3;
      mma_stageP<2,2,true,136,true,72>(Ah+cb*2176,Al+cb*2176,Bh+cb*1152,Bl+cb*1152,acc,wm,wn,lane);
    }
#undef KV_ISSUE
    float* C = g_KV + (size_t)(b*NC + c)*16384 + n0;
#pragma unroll
    for(int mt=0;mt<2;mt++){
      int r0 = wm*32+mt*16+gid;
#pragma unroll
      for(int nt=0;nt<4;nt++){
        int col = wn*32+nt*8+tig*2;
        float* a = acc[mt][nt];
        *(float2*)&C[(size_t)r0*128+col]     = make_float2(a[0],a[1]);
        *(float2*)&C[(size_t)(r0+8)*128+col] = make_float2(a[2],a[3]);
      }
    }
  }else{
    int r = vb - 128;
    int c = r & 31, b = (r>>5)&1, zz = r>>6;
    size_t base = ((size_t)b*TT + c*128)*128;
    bf* Ahp=(bf*)SB;            bf* Alp=(bf*)(SB+12288);
    bf* Bhp=(bf*)(SB+24576);    bf* Blp=(bf*)(SB+30720);
    float (*rs2s)[2] = (float(*)[2])(SB+36864);
    float acc[2][4][4];
#pragma unroll
    for(int i=0;i<2;i++)
#pragma unroll
      for(int j=0;j<4;j++)
#pragma unroll
        for(int k=0;k<4;k++) acc[i][j][k]=0.f;
    size_t bbase = base + (size_t)(zz*64)*128;
    cp_nat<128>(g_Qp_h,g_Qp_l, base, 128, 0, Ahp, Alp, tid);
    cp_nat<64> (g_Kp_h,g_Kp_l, bbase,128, 0, Bhp, Blp, tid);
    CPCOMMIT();
    for(int s=0;s<8;s++){
      CPWAIT(0);
      __syncthreads();
      if(s<7){
        int nb=(s+1)&1;
        cp_nat<128>(g_Qp_h,g_Qp_l, base, 128,(s+1)*16, Ahp+nb*3072, Alp+nb*3072, tid);
        cp_nat<64> (g_Kp_h,g_Kp_l, bbase,128,(s+1)*16, Bhp+nb*1536, Blp+nb*1536, tid);
        CPCOMMIT();
      }
      int cb=s&1;
      mma_stageP<2,2,false,24,false,24>(Ahp+cb*3072,Alp+cb*3072,Bhp+cb*1536,Blp+cb*1536,acc,wm,wn,lane);
    }
#pragma unroll
    for(int mt=0;mt<2;mt++){
      int r0 = wm*32+mt*16+gid;
      float s0=0.f, s1=0.f;
#pragma unroll
      for(int nt=0;nt<4;nt++){
        int col = zz*64 + wn*32 + nt*8 + tig*2;
        float* a = acc[mt][nt];
        float v0 = (col   <= r0  )? a[0] : 0.f;
        float v1 = (col+1 <= r0  )? a[1] : 0.f;
        float v2 = (col   <= r0+8)? a[2] : 0.f;
        float v3 = (col+1 <= r0+8)? a[3] : 0.f;
        s0 += v0+v1; s1 += v2+v3;
        bf2 lo;
        bf2 hi = split2(v0,v1,&lo);
        *(bf2*)&g_As_h[base + (size_t)r0*128+col] = hi;
        *(bf2*)&g_As_l[base + (size_t)r0*128+col] = lo;
        hi = split2(v2,v3,&lo);
        *(bf2*)&g_As_h[base + (size_t)(r0+8)*128+col] = hi;
        *(bf2*)&g_As_l[base + (size_t)(r0+8)*128+col] = lo;
      }
      s0 += __shfl_xor_sync(0xffffffffu, s0, 1); s0 += __shfl_xor_sync(0xffffffffu, s0, 2);
      s1 += __shfl_xor_sync(0xffffffffu, s1, 1); s1 += __shfl_xor_sync(0xffffffffu, s1, 2);
      if(tig==0){ rs2s[r0][wn]=s0; rs2s[r0+8][wn]=s1; }
    }
    __syncthreads();
    if(tid<128)
      g_rs[((size_t)b*TT + c*128 + tid)*2 + zz] = rs2s[tid][0] + rs2s[tid][1];
  }
}

__device__ void scan_phase(int vb, char* SB){
  float4 (*gt)[32] = (float4(*)[32])SB;
  int h = vb & 127, b = vb >> 7;
  int q = threadIdx.x & 31, g = threadIdx.x >> 5;
  size_t rowbase = (((size_t)b*NC)*128 + h)*128 + q*4;
  float4 v[4], pre[4];
#pragma unroll
  for(int j=0;j<4;j++) v[j] = *(const float4*)&g_KV[rowbase + (size_t)(g*4+j)*16384];
  float4 loc = make_float4(0.f,0.f,0.f,0.f);
#pragma unroll
  for(int j=0;j<4;j++){
    pre[j] = loc;
    loc.x += v[j].x; loc.y += v[j].y; loc.z += v[j].z; loc.w += v[j].w;
  }
  gt[g][q] = loc;
  __syncthreads();
  float4 off = make_float4(0.f,0.f,0.f,0.f);
#pragma unroll
  for(int gg=0;gg<7;gg++) if(gg < g){
    float4 t = gt[gg][q];
    off.x += t.x; off.y += t.y; off.z += t.z; off.w += t.w;
  }
#pragma unroll
  for(int j=0;j<4;j++){
    size_t i = rowbase + (size_t)(g*4+j)*16384;
    float a0 = off.x + pre[j].x, a1 = off.y + pre[j].y;
    float a2 = off.z + pre[j].z, a3 = off.w + pre[j].w;
    bf2 lo0, lo1;
    bf2 hi0 = split2(a0, a1, &lo0);
    bf2 hi1 = split2(a2, a3, &lo1);
    *(uint2*)&g_S_h[i] = make_uint2(bits2(hi0), bits2(hi1));
    *(uint2*)&g_S_l[i] = make_uint2(bits2(lo0), bits2(lo1));
  }
  if(threadIdx.x < NC){
    int mm = threadIdx.x;
    float ks = g_Ksum[(size_t)(b*NC + mm)*128 + h];
    float x = ks;
#pragma unroll
    for(int o=1;o<NC;o<<=1){
      float y = __shfl_up_sync(0xffffffffu, x, o);
      if(mm>=o) x += y;
    }
    g_KsumX[(size_t)(b*NC + mm)*128 + h] = x - ks;
  }
}

// num: 2Mx2N split, 4-stage pipeline. grid slice (NC,NB,4): q = mh*2+nh
__device__ void num_phase(int vb, char* SB){
  bf* Ah=(bf*)SB;          bf* Al=(bf*)(SB+12288);
  bf* Bh=(bf*)(SB+24576);  bf* Bl=(bf*)(SB+33792);
  float* kx  = (float*)(SB+43008);
  float* dsm = (float*)(SB+43520);
  int tid=threadIdx.x, lane=tid&31, wid=tid>>5;
  int wm=wid>>1, wn=wid&1;            // 4m x 2n warps over 64x64 tile
  int gid=lane>>2, tig=lane&3;
  int c = vb & 31, b = (vb>>5)&1, q = vb>>6;
  int mh = q>>1, nh = q&1;
  int m0 = mh*64, n0 = nh*64;
  size_t base  = ((size_t)b*TT + c*128)*128;
  size_t abasem = base + (size_t)m0*128;       // A rows m0..m0+63
  size_t sbase = (size_t)(b*NC + c)*16384;
  float acc[1][4][4];
#pragma unroll
  for(int j=0;j<4;j++)
#pragma unroll
    for(int k=0;k<4;k++) acc[0][j][k]=0.f;
  if(tid<128) kx[tid] = g_KsumX[(size_t)(b*NC + c)*128 + tid];
  float dd = 0.f;
#define NUM_ISSUE(s) { \
    if((s)<8){ \
      cp_nat<64>    (g_As_h,g_As_l, abasem,128,(s)*16,     Ah+((s)%4)*1536, Al+((s)%4)*1536, tid); \
      cp_trans<64,72>(g_Vg_h,g_Vg_l, base,  128,(s)*16, n0, Bh+((s)%4)*1152, Bl+((s)%4)*1152, tid); \
    }else{ \
      cp_nat<64>    (g_Qp_h,g_Qp_l, abasem,128,((s)-8)*16,     Ah+((s)%4)*1536, Al+((s)%4)*1536, tid); \
      cp_trans<64,72>(g_S_h, g_S_l, sbase, 128,((s)-8)*16, n0, Bh+((s)%4)*1152, Bl+((s)%4)*1152, tid); \
    } \
    CPCOMMIT(); }
  NUM_ISSUE(0); NUM_ISSUE(1); NUM_ISSUE(2);
  for(int s=0;s<16;s++){
    if(s<=13) CPWAIT(2); else if(s==14) CPWAIT(1); else CPWAIT(0);
    __syncthreads();
    if(s+3<16) NUM_ISSUE(s+3);
    int cb=s&3;
    mma_stageP<1,2,false,24,true,72>(Ah+cb*1536,Al+cb*1536,Bh+cb*1152,Bl+cb*1152,acc,wm,wn,lane);
    if(s>=8 && tid<64){
      const bf* ac  = Ah + cb*1536 + tid*24;
      const bf* alc = Al + cb*1536 + tid*24;
      int kb = (s-8)*16;
#pragma unroll
      for(int k=0;k<16;k++)
        dd += (__bfloat162float(ac[k])+__bfloat162float(alc[k])) * kx[kb+k];
    }
  }
#undef NUM_ISSUE
  if(tid<64){
    size_t bt2 = ((size_t)b*TT + c*128 + m0 + tid)*2;
    dsm[tid] = fmaxf(g_rs[bt2] + g_rs[bt2+1] + dd, 1e-6f);
  }
  __syncthreads();
  {
    int r0 = wm*16+gid;
    float inv0 = 1.f/dsm[r0], inv1 = 1.f/dsm[r0+8];
#pragma unroll
    for(int nt=0;nt<4;nt++){
      int col = n0 + wn*32 + nt*8 + tig*2;
      float* a = acc[0][nt];
      bf2 lo;
      bf2 hi = split2(a[0]*inv0, a[1]*inv0, &lo);
      *(bf2*)&g_at_h[abasem + (size_t)r0*128+col] = hi;
      *(bf2*)&g_at_l[abasem + (size_t)r0*128+col] = lo;
      hi = split2(a[2]*inv1, a[3]*inv1, &lo);
      *(bf2*)&g_at_h[abasem + (size_t)(r0+8)*128+col] = hi;
      *(bf2*)&g_at_l[abasem + (size_t)(r0+8)*128+col] = lo;
    }
  }
}

// wo: 128 blocks of 64 rows. Last layer: (vb&63)==63 -> pred.
__device__ void wo_phase(int vb, char* SB, int l,
                         const float* __restrict__ w2, const float* __restrict__ b2,
                         const float* __restrict__ w1, const float* __restrict__ b1,
                         int do_ln1, const float* __restrict__ pw, float* __restrict__ out){
  bf* Ahp=(bf*)SB;          bf* Alp=(bf*)(SB+6144);
  bf* Bhp=(bf*)(SB+12288);  bf* Blp=(bf*)(SB+24576);
  float (*Ps)[8] = (float(*)[8])(SB+36864);
  float (*Qs)[8] = (float(*)[8])(SB+38912);
  float* Mu = (float*)(SB+40960);
  float* Rv = (float*)(SB+41216);
  float* rr2 = (float*)(SB+41472);
  THREAD_IDS;
  float acc[1][8][4];
#pragma unroll
  for(int j=0;j<8;j++)
#pragma unroll
    for(int k=0;k<4;k++) acc[0][j][k]=0.f;
  size_t abase = (size_t)vb*64*128;
  size_t bbase = (size_t)l*16384;
  cp_nat<64> (g_at_h,g_at_l, abase,128, 0, Ahp, Alp, tid);
  cp_nat<128>(g_Wo_h,g_Wo_l, bbase,128, 0, Bhp, Blp, tid);
  CPCOMMIT();
  for(int s=0;s<8;s++){
    CPWAIT(0);
    __syncthreads();
    if(s<7){
      int nb=(s+1)&1;
      cp_nat<64> (g_at_h,g_at_l, abase,128,(s+1)*16, Ahp+nb*1536, Alp+nb*1536, tid);
      cp_nat<128>(g_Wo_h,g_Wo_l, bbase,128,(s+1)*16, Bhp+nb*3072, Blp+nb*3072, tid);
      CPCOMMIT();
    }
    int cb=s&1;
    mma_stageP<1,4,false,24,false,24>(Ahp+cb*1536,Alp+cb*1536,Bhp+cb*3072,Blp+cb*3072,acc,wm,wn,lane);
  }
  int slot = wn*4 + tig;
  size_t row0 = (size_t)vb*64;
  int rl0 = wm*16+gid;
  {
    float s0=0.f,q0=0.f,s1=0.f,q1=0.f;
#pragma unroll
    for(int nt=0;nt<8;nt++){
      int col = wn*64+nt*8+tig*2;
      float* a = acc[0][nt];
      float x0 = g_tokens[(row0+rl0)*128+col  ] + 0.1f*a[0];
      float x1 = g_tokens[(row0+rl0)*128+col+1] + 0.1f*a[1];
      float x2 = g_tokens[(row0+rl0+8)*128+col  ] + 0.1f*a[2];
      float x3 = g_tokens[(row0+rl0+8)*128+col+1] + 0.1f*a[3];
      a[0]=x0; a[1]=x1; a[2]=x2; a[3]=x3;
      s0 += x0+x1; q0 += x0*x0+x1*x1;
      s1 += x2+x3; q1 += x2*x2+x3*x3;
    }
    Ps[rl0][slot]=s0; Qs[rl0][slot]=q0;
    Ps[rl0+8][slot]=s1; Qs[rl0+8][slot]=q1;
  }
  __syncthreads();
  if(tid < 64){
    float s=0.f,q=0.f;
#pragma unroll
    for(int j=0;j<8;j++){ s+=Ps[tid][j]; q+=Qs[tid][j]; }
    float m = s*(1.f/128.f);
    float v = q*(1.f/128.f) - m*m;
    Mu[tid]=m; Rv[tid]=rsqrtf(v + 1e-5f);
  }
  __syncthreads();
  {
    float m0=Mu[rl0], i0=Rv[rl0], m1=Mu[rl0+8], i1=Rv[rl0+8];
    float s0=0.f,q0=0.f,s1=0.f,q1=0.f;
#pragma unroll
    for(int nt=0;nt<8;nt++){
      int col = wn*64+nt*8+tig*2;
      float* a = acc[0][nt];
      float w0=w2[col], w1_=w2[col+1], bb0=b2[col], bb1=b2[col+1];
      float y0=(a[0]-m0)*i0*w0+bb0, y1=(a[1]-m0)*i0*w1_+bb1;
      float y2=(a[2]-m1)*i1*w0+bb0, y3=(a[3]-m1)*i1*w1_+bb1;
      *(float2*)&g_tokens[(row0+rl0)*128+col]   = make_float2(y0,y1);
      *(float2*)&g_tokens[(row0+rl0+8)*128+col] = make_float2(y2,y3);
      a[0]=y0; a[1]=y1; a[2]=y2; a[3]=y3;
      s0 += y0+y1; q0 += y0*y0+y1*y1;
      s1 += y2+y3; q1 += y2*y2+y3*y3;
    }
    if(do_ln1){ Ps[rl0][slot]=s0; Qs[rl0][slot]=q0; Ps[rl0+8][slot]=s1; Qs[rl0+8][slot]=q1; }
  }
  if(!do_ln1){
    if((vb & 63) == 63){
      __syncthreads();
      int bb = vb >> 6;
      float v = 0.f;
      if(tid < 128) v = g_tokens[((size_t)bb*TT + (TT-1))*128 + tid] * pw[tid];
#pragma unroll
      for(int o=16;o>0;o>>=1) v += __shfl_down_sync(0xffffffffu, v, o);
      if(lane==0) rr2[wid]=v;
      __syncthreads();
      if(tid==0){
        float s=0.f;
#pragma unroll
        for(int j=0;j<8;j++) s+=rr2[j];
        out[bb] = s;
      }
    }
    return;
  }
  __syncthreads();
  if(tid < 64){
    float s=0.f,q=0.f;
#pragma unroll
    for(int j=0;j<8;j++){ s+=Ps[tid][j]; q+=Qs[tid][j]; }
    float m = s*(1.f/128.f);
    float v = q*(1.f/128.f) - m*m;
    Mu[tid]=m; Rv[tid]=rsqrtf(v + 1e-5f);
  }
  __syncthreads();
  {
    float m0=Mu[rl0], i0=Rv[rl0], m1=Mu[rl0+8], i1=Rv[rl0+8];
#pragma unroll
    for(int nt=0;nt<8;nt++){
      int col = wn*64+nt*8+tig*2;
      float* a = acc[0][nt];
      float w0=w1[col], w1_=w1[col+1], bb0=b1[col], bb1=b1[col+1];
      float y0=(a[0]-m0)*i0*w0+bb0, y1=(a[1]-m0)*i0*w1_+bb1;
      float y2=(a[2]-m1)*i1*w0+bb0, y3=(a[3]-m1)*i1*w1_+bb1;
      bf2 lo;
      bf2 hi = split2(y0,y1,&lo);
      *(bf2*)&g_x_h[(row0+rl0)*128+col] = hi;
      *(bf2*)&g_x_l[(row0+rl0)*128+col] = lo;
      hi = split2(y2,y3,&lo);
      *(bf2*)&g_x_h[(row0+rl0+8)*128+col] = hi;
      *(bf2*)&g_x_l[(row0+rl0+8)*128+col] = lo;
    }
  }
}

// ================= mega kernel: both layers, device barriers ================
__global__ void __launch_bounds__(256,2)
mega_kernel(const float* __restrict__ Wgb,
            const float* __restrict__ ln1w, const float* __restrict__ ln1b,
            const float* __restrict__ ln2w, const float* __restrict__ ln2b,
            const float* __restrict__ pw, float* __restrict__ out){
  extern __shared__ char SB[];
  int vb = blockIdx.x;
  unsigned bar = 0;
  for(int l=0;l<2;l++){
    proj_phase(vb, SB, l, Wgb + l*128);
    gsync(++bar);
    chunk1_phase(vb, SB);
    gsync(++bar);
    scan_phase(vb, SB);
    gsync(++bar);
    num_phase(vb, SB);
    gsync(++bar);
    if(vb < 128)
      wo_phase(vb, SB, l, ln2w + l*128, ln2b + l*128,
               ln1w + (l+1<2?(l+1):l)*128, ln1b + (l+1<2?(l+1):l)*128,
               l+1 < 2, pw, out);
    if(l==0) gsync(++bar);
  }
}

// ----------------- launch -----------------
extern "C" void kernel_launch(void* const* d_in, const int* in_sizes, int n_in,
                              void* d_out, int out_size){
  const float* xs   = (const float*)d_in[0];
  const float* ys   = (const float*)d_in[1];
  const float* qx   = (const float*)d_in[2];
  const float* Wq   = (const float*)d_in[3];
  const float* Wk   = (const float*)d_in[4];
  const float* Wv   = (const float*)d_in[5];
  const float* Wgw  = (const float*)d_in[6];
  const float* Wgb  = (const float*)d_in[7];
  const float* Wo   = (const float*)d_in[8];
  const float* ln1w = (const float*)d_in[9];
  const float* ln1b = (const float*)d_in[10];
  const float* ln2w = (const float*)d_in[11];
  const float* ln2b = (const float*)d_in[12];
  const float* pw   = (const float*)d_in[13];
  float* out = (float*)d_out;

  build_all<<<1664, 256>>>(xs, ys, qx, Wq, Wk, Wv, Wgw, Wo, ln1w, ln1b);
  mega_kernel<<<256, 256, 49152>>>(Wgb, ln1w, ln1b, ln2w, ln2b, pw, out);
}